// round 6
// baseline (speedup 1.0000x reference)
#include <cuda_runtime.h>
#include <cuda_bf16.h>
#include <math.h>
#include <stdint.h>

// Problem constants
constexpr int B_  = 4;
constexpr int T_  = 2048;
constexpr int D_  = 1024;
constexpr int H_  = 16;
constexpr int DH_ = 64;
constexpr int M_  = B_ * T_;   // 8192
constexpr int N_  = D_;        // 1024
constexpr int K_  = D_;        // 1024
constexpr int KP_ = K_ / 2;    // 512 k-pairs

// Scratch (device globals: allocation-free per harness rules).
__device__ float    g_q [M_ * D_];
__device__ float    g_k [M_ * D_];
__device__ float    g_v [M_ * D_];
__device__ float    g_vT[M_ * D_];           // [B][D][T]
__device__ uint32_t g_kh[KP_ * M_];           // K packed hi [B][H][32][T]
__device__ uint32_t g_kl[KP_ * M_];           // K packed lo
__device__ uint32_t g_ah[KP_ * M_];           // x packed hi  [K/2][M]
__device__ uint32_t g_al[KP_ * M_];           // x packed lo
__device__ uint32_t g_ch[KP_ * M_];           // ctx packed hi [D/2][M]
__device__ uint32_t g_cl[KP_ * M_];           // ctx packed lo
__device__ uint32_t g_wh[4 * KP_ * N_];       // weights packed hi [z][K/2][N]
__device__ uint32_t g_wl[4 * KP_ * N_];       // weights packed lo

// ---------------------------------------------------------------------------
// Helpers
// ---------------------------------------------------------------------------
#define MMA_TF32(d, a, b)                                                    \
    asm volatile(                                                            \
        "mma.sync.aligned.m16n8k8.row.col.f32.tf32.tf32.f32 "                \
        "{%0,%1,%2,%3}, {%4,%5,%6,%7}, {%8,%9}, {%0,%1,%2,%3};"              \
        : "+f"((d)[0]), "+f"((d)[1]), "+f"((d)[2]), "+f"((d)[3])             \
        : "r"((a)[0]), "r"((a)[1]), "r"((a)[2]), "r"((a)[3]),                \
          "r"((b)[0]), "r"((b)[1]))

#define MMA_BF16(d, a, b)                                                    \
    asm volatile(                                                            \
        "mma.sync.aligned.m16n8k16.row.col.f32.bf16.bf16.f32 "               \
        "{%0,%1,%2,%3}, {%4,%5,%6,%7}, {%8,%9}, {%0,%1,%2,%3};"              \
        : "+f"((d)[0]), "+f"((d)[1]), "+f"((d)[2]), "+f"((d)[3])             \
        : "r"((a)[0]), "r"((a)[1]), "r"((a)[2]), "r"((a)[3]),                \
          "r"((b)[0]), "r"((b)[1]))

#define CP_ASYNC16(dst, src)                                                 \
    asm volatile("cp.async.cg.shared.global [%0], [%1], 16;"                 \
                 :: "r"(dst), "l"(src))
#define CP_COMMIT()  asm volatile("cp.async.commit_group;")
#define CP_WAIT2()   asm volatile("cp.async.wait_group 2;")

__device__ __forceinline__ uint32_t smem_u32(const void* p) {
    return (uint32_t)__cvta_generic_to_shared(p);
}

__device__ __forceinline__ float rna_tf32(float x) {
    uint32_t u = __float_as_uint(x);
    u = (u + 0x1000u) & 0xFFFFE000u;
    return __uint_as_float(u);
}

// Split (a,b) into bf16 hi pair + bf16 lo-residual pair, packed bf16x2.
__device__ __forceinline__ void packpair_bf16(float a, float b,
                                              uint32_t& h, uint32_t& l) {
    const float ha = __bfloat162float(__float2bfloat16(a));
    const float hb = __bfloat162float(__float2bfloat16(b));
    __nv_bfloat162 H = __floats2bfloat162_rn(ha, hb);
    __nv_bfloat162 L = __floats2bfloat162_rn(a - ha, b - hb);
    h = *reinterpret_cast<uint32_t*>(&H);
    l = *reinterpret_cast<uint32_t*>(&L);
}

// ---------------------------------------------------------------------------
// Packing kernels
// ---------------------------------------------------------------------------
// x [M][K] fp32 -> g_ah/g_al [K/2][M] packed bf16x2 (transpose)
__global__ __launch_bounds__(256)
void pack_x(const float* __restrict__ x) {
    __shared__ uint32_t th[32][33], tl[32][33];
    const int m0  = blockIdx.x * 32;
    const int kp0 = blockIdx.y * 32;
    const int tx  = threadIdx.x;
    const int ty  = threadIdx.y;
#pragma unroll
    for (int i = 0; i < 4; ++i) {
        const int m = ty + i * 8;
        float2 v = *reinterpret_cast<const float2*>(
            &x[(size_t)(m0 + m) * K_ + (size_t)(kp0 + tx) * 2]);
        packpair_bf16(v.x, v.y, th[tx][m], tl[tx][m]);
    }
    __syncthreads();
#pragma unroll
    for (int i = 0; i < 4; ++i) {
        const int kp = ty + i * 8;
        g_ah[(size_t)(kp0 + kp) * M_ + m0 + tx] = th[kp][tx];
        g_al[(size_t)(kp0 + kp) * M_ + m0 + tx] = tl[kp][tx];
    }
}

// W [K][N] fp32 -> packed [K/2][N]
__global__ __launch_bounds__(256)
void pack_w(const float* __restrict__ Wq, const float* __restrict__ Wk,
            const float* __restrict__ Wv, const float* __restrict__ Wo) {
    const int z = blockIdx.z;
    const float* W = (z == 0) ? Wq : (z == 1) ? Wk : (z == 2) ? Wv : Wo;
    const int n  = blockIdx.x * 256 + threadIdx.x;
    const int kp = blockIdx.y;
    uint32_t h, l;
    packpair_bf16(W[(size_t)(2 * kp) * N_ + n],
                  W[(size_t)(2 * kp + 1) * N_ + n], h, l);
    const size_t o = (size_t)z * KP_ * N_ + (size_t)kp * N_ + n;
    g_wh[o] = h;
    g_wl[o] = l;
}

// g_k [B][T][D] -> g_kh/g_kl [B][512][T] (d-pairs, transposed to t-major)
__global__ __launch_bounds__(256)
void pack_k() {
    __shared__ uint32_t th[32][33], tl[32][33];
    const int b   = blockIdx.z;
    const int t0  = blockIdx.x * 32;
    const int dp0 = blockIdx.y * 32;
    const int tx  = threadIdx.x;
    const int ty  = threadIdx.y;
#pragma unroll
    for (int i = 0; i < 4; ++i) {
        const int tt = ty + i * 8;
        float2 v = *reinterpret_cast<const float2*>(
            &g_k[(size_t)(b * T_ + t0 + tt) * D_ + (size_t)(dp0 + tx) * 2]);
        packpair_bf16(v.x, v.y, th[tx][tt], tl[tx][tt]);
    }
    __syncthreads();
#pragma unroll
    for (int i = 0; i < 4; ++i) {
        const int dp = ty + i * 8;
        const size_t o = ((size_t)b * 512 + dp0 + dp) * T_ + t0 + tx;
        g_kh[o] = th[dp][tx];
        g_kl[o] = tl[dp][tx];
    }
}

// V transpose: g_vT[b][d][t] = rna_tf32(g_v[b][t][d])
__global__ __launch_bounds__(256)
void transpose_v() {
    __shared__ float tile[32][33];
    const int b  = blockIdx.z;
    const int t0 = blockIdx.x * 32;
    const int d0 = blockIdx.y * 32;
    const int tx = threadIdx.x;
    const int ty = threadIdx.y;
#pragma unroll
    for (int i = 0; i < 32; i += 8)
        tile[ty + i][tx] = g_v[(size_t)b * T_ * D_ + (size_t)(t0 + ty + i) * D_ + d0 + tx];
    __syncthreads();
#pragma unroll
    for (int i = 0; i < 32; i += 8)
        g_vT[(size_t)b * D_ * T_ + (size_t)(d0 + ty + i) * T_ + t0 + tx] =
            rna_tf32(tile[tx][ty + i]);
}

// ---------------------------------------------------------------------------
// 3xBF16 GEMM, cp.async 4-stage pipeline (1 barrier / k-step).
// ---------------------------------------------------------------------------
constexpr int SSTR   = 136;
constexpr int STAGES = 4;
constexpr int ST_U32 = 4 * 8 * SSTR;
constexpr int OFF_AL = 8 * SSTR;
constexpr int OFF_BH = 16 * SSTR;
constexpr int OFF_BL = 24 * SSTR;

__device__ __forceinline__ void tgemm_body(const uint32_t* __restrict__ Ah,
                                           const uint32_t* __restrict__ Al,
                                           const uint32_t* __restrict__ Bh,
                                           const uint32_t* __restrict__ Bl,
                                           float* __restrict__ C,
                                           const float* __restrict__ bias) {
    extern __shared__ uint32_t smp[];
    const uint32_t sb0 = smem_u32(smp);

    const int t    = threadIdx.x;
    const int lane = t & 31;
    const int wid  = t >> 5;
    const int wM   = wid & 1;
    const int wN   = wid >> 1;
    const int g    = lane >> 2;
    const int tg   = lane & 3;

    const int r0 = blockIdx.y * 128;
    const int c0 = blockIdx.x * 128;

    const int crow = t >> 5;
    const int cc4  = (t & 31) * 4;

    float acc[4][4][4];
#pragma unroll
    for (int i = 0; i < 4; ++i)
#pragma unroll
        for (int j = 0; j < 4; ++j)
#pragma unroll
            for (int r = 0; r < 4; ++r) acc[i][j][r] = 0.f;

    const int NT = K_ / 16;

    auto issue = [&](int kt, int buf) {
        const uint32_t db = sb0 + (uint32_t)(buf * ST_U32 + crow * SSTR + cc4) * 4u;
        const size_t kr = (size_t)(kt * 8 + crow);
        CP_ASYNC16(db,               Ah + kr * M_ + r0 + cc4);
        CP_ASYNC16(db + OFF_AL * 4u, Al + kr * M_ + r0 + cc4);
        CP_ASYNC16(db + OFF_BH * 4u, Bh + kr * N_ + c0 + cc4);
        CP_ASYNC16(db + OFF_BL * 4u, Bl + kr * N_ + c0 + cc4);
    };

#pragma unroll
    for (int s = 0; s < STAGES - 1; ++s) {
        issue(s, s);
        CP_COMMIT();
    }

    for (int kt = 0; kt < NT; ++kt) {
        CP_WAIT2();
        __syncthreads();   // sole barrier: separates buffer reuse epochs

        const uint32_t* sA_hi = smp + (kt % STAGES) * ST_U32;
        const uint32_t* sA_lo = sA_hi + OFF_AL;
        const uint32_t* sB_hi = sA_hi + OFF_BH;
        const uint32_t* sB_lo = sA_hi + OFF_BL;

        uint32_t bh[4][2], bl[4][2];
#pragma unroll
        for (int nf = 0; nf < 4; ++nf) {
            const int cc = wN * 32 + nf * 8 + g;
            bh[nf][0] = sB_hi[tg * SSTR + cc];
            bh[nf][1] = sB_hi[(tg + 4) * SSTR + cc];
            bl[nf][0] = sB_lo[tg * SSTR + cc];
            bl[nf][1] = sB_lo[(tg + 4) * SSTR + cc];
        }
#pragma unroll
        for (int mf = 0; mf < 4; ++mf) {
            const int rb = wM * 64 + mf * 16 + g;
            uint32_t ah[4], al[4];
            ah[0] = sA_hi[tg * SSTR + rb];
            ah[1] = sA_hi[tg * SSTR + rb + 8];
            ah[2] = sA_hi[(tg + 4) * SSTR + rb];
            ah[3] = sA_hi[(tg + 4) * SSTR + rb + 8];
            al[0] = sA_lo[tg * SSTR + rb];
            al[1] = sA_lo[tg * SSTR + rb + 8];
            al[2] = sA_lo[(tg + 4) * SSTR + rb];
            al[3] = sA_lo[(tg + 4) * SSTR + rb + 8];
#pragma unroll
            for (int nf = 0; nf < 4; ++nf) {
                MMA_BF16(acc[mf][nf], al, bh[nf]);
                MMA_BF16(acc[mf][nf], ah, bl[nf]);
                MMA_BF16(acc[mf][nf], ah, bh[nf]);
            }
        }

        const int kn = kt + STAGES - 1;
        if (kn < NT) issue(kn, kn % STAGES);
        CP_COMMIT();
    }

#pragma unroll
    for (int mf = 0; mf < 4; ++mf) {
#pragma unroll
        for (int nf = 0; nf < 4; ++nf) {
            const int row = r0 + wM * 64 + mf * 16 + g;
            const int col = c0 + wN * 32 + nf * 8 + 2 * tg;
            float2 v0 = make_float2(acc[mf][nf][0], acc[mf][nf][1]);
            float2 v1 = make_float2(acc[mf][nf][2], acc[mf][nf][3]);
            if (bias) {
                const float b0v = bias[col], b1v = bias[col + 1];
                v0.x += b0v; v0.y += b1v;
                v1.x += b0v; v1.y += b1v;
            }
            *reinterpret_cast<float2*>(&C[(size_t)row * N_ + col])       = v0;
            *reinterpret_cast<float2*>(&C[(size_t)(row + 8) * N_ + col]) = v1;
        }
    }
}

__global__ __launch_bounds__(256, 2)
void tgemm_qkv() {
    const int z = blockIdx.z;
    float* C = (z == 0) ? g_q : (z == 1) ? g_k : g_v;
    tgemm_body(g_ah, g_al,
               g_wh + (size_t)z * KP_ * N_, g_wl + (size_t)z * KP_ * N_,
               C, nullptr);
}

__global__ __launch_bounds__(256, 2)
void tgemm_out(const float* __restrict__ bo, float* __restrict__ out) {
    tgemm_body(g_ch, g_cl,
               g_wh + (size_t)3 * KP_ * N_, g_wl + (size_t)3 * KP_ * N_,
               out, bo);
}

// ---------------------------------------------------------------------------
// Tensor-core causal flash attention.
// QK^T: 3xBF16 m16n8k16 (K pre-packed hi/lo; Q split once in regs).
// PV:   tf32 m16n8k8 (P rna-tf32 via warp-private smem, V^T rna-tf32).
// Writes ctx PACKED bf16 hi/lo [D/2][M] for the out-projection GEMM.
// ---------------------------------------------------------------------------
constexpr int FSTR = 68;   // fp32 row stride (Q/Ps and Vt)
constexpr int KSTR = 72;   // u32 row stride for K tiles (conflict-free: 72%32=8)
constexpr int SM_QS = 0;                    // 64*FSTR fp32
constexpr int SM_KH = 64 * FSTR;            // 32*KSTR u32
constexpr int SM_KL = SM_KH + 32 * KSTR;    // 32*KSTR u32
constexpr int SM_VT = SM_KL + 32 * KSTR;    // 64*FSTR fp32
constexpr int SM_AT = SM_VT + 64 * FSTR;    // total words

__global__ __launch_bounds__(128)
void flash_attn_tc() {
    extern __shared__ float sm[];
    float*    Qs = sm + SM_QS;
    uint32_t* Kh = reinterpret_cast<uint32_t*>(sm + SM_KH);
    uint32_t* Kl = reinterpret_cast<uint32_t*>(sm + SM_KL);
    float*    Vt = sm + SM_VT;

    const int t    = threadIdx.x;
    const int lane = t & 31;
    const int w    = t >> 5;
    const int g    = lane >> 2;
    const int tg   = lane & 3;

    const int qb = (int)gridDim.x - 1 - (int)blockIdx.x;
    const int hh = blockIdx.y;
    const int b  = blockIdx.z;
    const int q0 = qb * 64;
    const size_t qbase = (size_t)b * T_ * D_ + (size_t)hh * DH_;
    const size_t vtb   = (size_t)b * D_ * T_ + (size_t)hh * DH_ * T_;
    const size_t kbb   = ((size_t)b * 512 + hh * 32) * T_;

    // Stage Q (scaled by 1/sqrt(64))
    for (int idx = t; idx < 64 * 16; idx += 128) {
        const int r = idx >> 4, c4 = (idx & 15) * 4;
        float4 v = *reinterpret_cast<const float4*>(
            &g_q[qbase + (size_t)(q0 + r) * D_ + c4]);
        v.x *= 0.125f; v.y *= 0.125f; v.z *= 0.125f; v.w *= 0.125f;
        *reinterpret_cast<float4*>(&Qs[r * FSTR + c4]) = v;
    }
    __syncthreads();

    // Q -> bf16 hi/lo k16 A-fragments (4 k-steps), split once
    const int r0 = w * 16 + g;
    const int r1 = r0 + 8;
    uint32_t qh[4][4], ql[4][4];
#pragma unroll
    for (int ks = 0; ks < 4; ++ks) {
        const int c = ks * 16 + 2 * tg;
        packpair_bf16(Qs[r0 * FSTR + c],     Qs[r0 * FSTR + c + 1],
                      qh[ks][0], ql[ks][0]);
        packpair_bf16(Qs[r1 * FSTR + c],     Qs[r1 * FSTR + c + 1],
                      qh[ks][1], ql[ks][1]);
        packpair_bf16(Qs[r0 * FSTR + c + 8], Qs[r0 * FSTR + c + 9],
                      qh[ks][2], ql[ks][2]);
        packpair_bf16(Qs[r1 * FSTR + c + 8], Qs[r1 * FSTR + c + 9],
                      qh[ks][3], ql[ks][3]);
    }

    float o[8][4];
#pragma unroll
    for (int nf = 0; nf < 8; ++nf)
#pragma unroll
        for (int r = 0; r < 4; ++r) o[nf][r] = 0.f;
    float m0 = -1e30f, m1 = -1e30f, l0 = 0.f, l1 = 0.f;

    const int ntiles = qb + 1;
    for (int kt = 0; kt < ntiles; ++kt) {
        // Load K tile (packed u32, [dp][kv]) and V^T tile (fp32, [d][kv])
        for (int idx = t; idx < 512; idx += 128) {
            const int r = idx >> 4, c4 = (idx & 15) * 4;
            const size_t gk = kbb + (size_t)r * T_ + kt * 64 + c4;
            *reinterpret_cast<uint4*>(&Kh[r * KSTR + c4]) =
                *reinterpret_cast<const uint4*>(&g_kh[gk]);
            *reinterpret_cast<uint4*>(&Kl[r * KSTR + c4]) =
                *reinterpret_cast<const uint4*>(&g_kl[gk]);
        }
        for (int idx = t; idx < 64 * 16; idx += 128) {
            const int r = idx >> 4, c4 = (idx & 15) * 4;
            *reinterpret_cast<float4*>(&Vt[r * FSTR + c4]) =
                *reinterpret_cast<const float4*>(
                    &g_vT[vtb + (size_t)r * T_ + kt * 64 + c4]);
        }
        __syncthreads();

        // S = Q K^T (3xBF16, 96 MMAs)
        float s[8][4];
#pragma unroll
        for (int nf = 0; nf < 8; ++nf)
#pragma unroll
            for (int r = 0; r < 4; ++r) s[nf][r] = 0.f;

#pragma unroll
        for (int ks = 0; ks < 4; ++ks) {
#pragma unroll
            for (int nf = 0; nf < 8; ++nf) {
                const int cc = nf * 8 + g;
                uint32_t bh[2], bl[2];
                bh[0] = Kh[(ks * 8 + tg) * KSTR + cc];
                bh[1] = Kh[(ks * 8 + tg + 4) * KSTR + cc];
                bl[0] = Kl[(ks * 8 + tg) * KSTR + cc];
                bl[1] = Kl[(ks * 8 + tg + 4) * KSTR + cc];
                MMA_BF16(s[nf], ql[ks], bh);
                MMA_BF16(s[nf], qh[ks], bl);
                MMA_BF16(s[nf], qh[ks], bh);
            }
        }

        // Causal mask (diagonal tile)
        if (kt == qb) {
#pragma unroll
            for (int nf = 0; nf < 8; ++nf) {
                const int c = nf * 8 + 2 * tg;
                if (c     > r0) s[nf][0] = -1e30f;
                if (c + 1 > r0) s[nf][1] = -1e30f;
                if (c     > r1) s[nf][2] = -1e30f;
                if (c + 1 > r1) s[nf][3] = -1e30f;
            }
        }

        // Online softmax
        float mx0 = -1e30f, mx1 = -1e30f;
#pragma unroll
        for (int nf = 0; nf < 8; ++nf) {
            mx0 = fmaxf(mx0, fmaxf(s[nf][0], s[nf][1]));
            mx1 = fmaxf(mx1, fmaxf(s[nf][2], s[nf][3]));
        }
        mx0 = fmaxf(mx0, __shfl_xor_sync(0xffffffffu, mx0, 1));
        mx0 = fmaxf(mx0, __shfl_xor_sync(0xffffffffu, mx0, 2));
        mx1 = fmaxf(mx1, __shfl_xor_sync(0xffffffffu, mx1, 1));
        mx1 = fmaxf(mx1, __shfl_xor_sync(0xffffffffu, mx1, 2));
        const float mn0 = fmaxf(m0, mx0);
        const float mn1 = fmaxf(m1, mx1);
        const float a0 = __expf(m0 - mn0);
        const float a1 = __expf(m1 - mn1);

        float rs0 = 0.f, rs1 = 0.f;
#pragma unroll
        for (int nf = 0; nf < 8; ++nf) {
            s[nf][0] = __expf(s[nf][0] - mn0); rs0 += s[nf][0];
            s[nf][1] = __expf(s[nf][1] - mn0); rs0 += s[nf][1];
            s[nf][2] = __expf(s[nf][2] - mn1); rs1 += s[nf][2];
            s[nf][3] = __expf(s[nf][3] - mn1); rs1 += s[nf][3];
            o[nf][0] *= a0; o[nf][1] *= a0;
            o[nf][2] *= a1; o[nf][3] *= a1;
        }
        rs0 += __shfl_xor_sync(0xffffffffu, rs0, 1);
        rs0 += __shfl_xor_sync(0xffffffffu, rs0, 2);
        rs1 += __shfl_xor_sync(0xffffffffu, rs1, 1);
        rs1 += __shfl_xor_sync(0xffffffffu, rs1, 2);
        l0 = l0 * a0 + rs0;
        l1 = l1 * a1 + rs1;
        m0 = mn0; m1 = mn1;

        // Stage P (rna tf32) in warp-private smem rows
        float* Ps = Qs;
#pragma unroll
        for (int nf = 0; nf < 8; ++nf) {
            const int c = nf * 8 + 2 * tg;
            Ps[r0 * FSTR + c]     = rna_tf32(s[nf][0]);
            Ps[r0 * FSTR + c + 1] = rna_tf32(s[nf][1]);
            Ps[r1 * FSTR + c]     = rna_tf32(s[nf][2]);
            Ps[r1 * FSTR + c + 1] = rna_tf32(s[nf][3]);
        }

        // O += P V (tf32, 64 MMAs)
#pragma unroll
        for (int k = 0; k < 8; ++k) {
            uint32_t pa[4];
            pa[0] = __float_as_uint(Ps[r0 * FSTR + k * 8 + tg]);
            pa[1] = __float_as_uint(Ps[r1 * FSTR + k * 8 + tg]);
            pa[2] = __float_as_uint(Ps[r0 * FSTR + k * 8 + tg + 4]);
            pa[3] = __float_as_uint(Ps[r1 * FSTR + k * 8 + tg + 4]);
#pragma unroll
            for (int nf = 0; nf < 8; ++nf) {
                uint32_t vb[2];
                vb[0] = __float_as_uint(Vt[(nf * 8 + g) * FSTR + k * 8 + tg]);
                vb[1] = __float_as_uint(Vt[(nf * 8 + g) * FSTR + k * 8 + tg + 4]);
                MMA_TF32(o[nf], pa, vb);
            }
        }
        __syncthreads();
    }

    // Normalize + write ctx packed [D/2][M]
    const float i0 = 1.f / l0;
    const float i1 = 1.f / l1;
    const int mg = b * T_ + q0;
#pragma unroll
    for (int nf = 0; nf < 8; ++nf) {
        const int col = hh * DH_ + nf * 8 + 2 * tg;
        const size_t kp = (size_t)(col >> 1) * M_;
        uint32_t ph, pl;
        packpair_bf16(o[nf][0] * i0, o[nf][1] * i0, ph, pl);
        g_ch[kp + mg + r0] = ph;
        g_cl[kp + mg + r0] = pl;
        packpair_bf16(o[nf][2] * i1, o[nf][3] * i1, ph, pl);
        g_ch[kp + mg + r1] = ph;
        g_cl[kp + mg + r1] = pl;
    }
}

// ---------------------------------------------------------------------------
extern "C" void kernel_launch(void* const* d_in, const int* in_sizes, int n_in,
                              void* d_out, int out_size) {
    const float* x  = (const float*)d_in[0];
    const float* Wq = (const float*)d_in[1];
    const float* Wk = (const float*)d_in[2];
    const float* Wv = (const float*)d_in[3];
    const float* Wo = (const float*)d_in[4];
    const float* bo = (const float*)d_in[5];
    float* out = (float*)d_out;

    // 0) Pack x and weights
    pack_x<<<dim3(M_ / 32, KP_ / 32), dim3(32, 8)>>>(x);
    pack_w<<<dim3(N_ / 256, KP_, 4), 256>>>(Wq, Wk, Wv, Wo);

    const int gsmem = STAGES * ST_U32 * 4;
    cudaFuncSetAttribute(tgemm_qkv,
                         cudaFuncAttributeMaxDynamicSharedMemorySize, gsmem);
    cudaFuncSetAttribute(tgemm_out,
                         cudaFuncAttributeMaxDynamicSharedMemorySize, gsmem);

    // 1) QKV projections
    tgemm_qkv<<<dim3(N_ / 128, M_ / 128, 3), 256, gsmem>>>();

    // 2) Pack K (bf16 hi/lo, t-major) and transpose V (tf32)
    pack_k<<<dim3(T_ / 32, 16, B_), dim3(32, 8)>>>();
    transpose_v<<<dim3(T_ / 32, D_ / 32, B_), dim3(32, 8)>>>();

    // 3) Attention (writes packed ctx)
    const int asmem = SM_AT * sizeof(float);   // 53,248 B
    cudaFuncSetAttribute(flash_attn_tc,
                         cudaFuncAttributeMaxDynamicSharedMemorySize, asmem);
    flash_attn_tc<<<dim3(T_ / 64, H_, B_), 128, asmem>>>();

    // 4) Output projection (+bias)
    tgemm_out<<<dim3(N_ / 128, M_ / 128), 256, gsmem>>>(bo, out);
}

// round 7
// speedup vs baseline: 1.1726x; 1.1726x over previous
#include <cuda_runtime.h>
#include <cuda_bf16.h>
#include <math.h>
#include <stdint.h>

// Problem constants
constexpr int B_  = 4;
constexpr int T_  = 2048;
constexpr int D_  = 1024;
constexpr int H_  = 16;
constexpr int DH_ = 64;
constexpr int M_  = B_ * T_;   // 8192
constexpr int N_  = D_;        // 1024
constexpr int K_  = D_;        // 1024
constexpr int KP_ = K_ / 2;    // 512

// Scratch (device globals: allocation-free per harness rules).
__device__ float    g_q [M_ * D_];            // Q fp32 [B][T][D]
__device__ float    g_vT[M_ * D_];            // V^T tf32 [B][D][T]
__device__ uint32_t g_kh[KP_ * M_];           // K packed hi [B][512][T]
__device__ uint32_t g_kl[KP_ * M_];           // K packed lo
__device__ uint32_t g_ah[KP_ * M_];           // x packed hi  [K/2][M]
__device__ uint32_t g_al[KP_ * M_];           // x packed lo
__device__ uint32_t g_ch[KP_ * M_];           // ctx packed hi [D/2][M]
__device__ uint32_t g_cl[KP_ * M_];           // ctx packed lo
__device__ uint32_t g_wh[4 * KP_ * N_];       // weights packed hi [z][K/2][N]
__device__ uint32_t g_wl[4 * KP_ * N_];       // weights packed lo

// ---------------------------------------------------------------------------
// Helpers
// ---------------------------------------------------------------------------
#define MMA_TF32(d, a, b)                                                    \
    asm volatile(                                                            \
        "mma.sync.aligned.m16n8k8.row.col.f32.tf32.tf32.f32 "                \
        "{%0,%1,%2,%3}, {%4,%5,%6,%7}, {%8,%9}, {%0,%1,%2,%3};"              \
        : "+f"((d)[0]), "+f"((d)[1]), "+f"((d)[2]), "+f"((d)[3])             \
        : "r"((a)[0]), "r"((a)[1]), "r"((a)[2]), "r"((a)[3]),                \
          "r"((b)[0]), "r"((b)[1]))

#define MMA_BF16(d, a, b)                                                    \
    asm volatile(                                                            \
        "mma.sync.aligned.m16n8k16.row.col.f32.bf16.bf16.f32 "               \
        "{%0,%1,%2,%3}, {%4,%5,%6,%7}, {%8,%9}, {%0,%1,%2,%3};"              \
        : "+f"((d)[0]), "+f"((d)[1]), "+f"((d)[2]), "+f"((d)[3])             \
        : "r"((a)[0]), "r"((a)[1]), "r"((a)[2]), "r"((a)[3]),                \
          "r"((b)[0]), "r"((b)[1]))

#define CP_ASYNC16(dst, src)                                                 \
    asm volatile("cp.async.cg.shared.global [%0], [%1], 16;"                 \
                 :: "r"(dst), "l"(src))
#define CP_COMMIT()  asm volatile("cp.async.commit_group;")
#define CP_WAIT0()   asm volatile("cp.async.wait_group 0;")
#define CP_WAIT1()   asm volatile("cp.async.wait_group 1;")
#define CP_WAIT2()   asm volatile("cp.async.wait_group 2;")

__device__ __forceinline__ uint32_t smem_u32(const void* p) {
    return (uint32_t)__cvta_generic_to_shared(p);
}

__device__ __forceinline__ float rna_tf32(float x) {
    uint32_t u = __float_as_uint(x);
    u = (u + 0x1000u) & 0xFFFFE000u;
    return __uint_as_float(u);
}

__device__ __forceinline__ void packpair_bf16(float a, float b,
                                              uint32_t& h, uint32_t& l) {
    const float ha = __bfloat162float(__float2bfloat16(a));
    const float hb = __bfloat162float(__float2bfloat16(b));
    __nv_bfloat162 H = __floats2bfloat162_rn(ha, hb);
    __nv_bfloat162 L = __floats2bfloat162_rn(a - ha, b - hb);
    h = *reinterpret_cast<uint32_t*>(&H);
    l = *reinterpret_cast<uint32_t*>(&L);
}

// ---------------------------------------------------------------------------
// Packing kernels (inputs only)
// ---------------------------------------------------------------------------
__global__ __launch_bounds__(256)
void pack_x(const float* __restrict__ x) {
    __shared__ uint32_t th[32][33], tl[32][33];
    const int m0  = blockIdx.x * 32;
    const int kp0 = blockIdx.y * 32;
    const int tx  = threadIdx.x;
    const int ty  = threadIdx.y;
#pragma unroll
    for (int i = 0; i < 4; ++i) {
        const int m = ty + i * 8;
        float2 v = *reinterpret_cast<const float2*>(
            &x[(size_t)(m0 + m) * K_ + (size_t)(kp0 + tx) * 2]);
        packpair_bf16(v.x, v.y, th[tx][m], tl[tx][m]);
    }
    __syncthreads();
#pragma unroll
    for (int i = 0; i < 4; ++i) {
        const int kp = ty + i * 8;
        g_ah[(size_t)(kp0 + kp) * M_ + m0 + tx] = th[kp][tx];
        g_al[(size_t)(kp0 + kp) * M_ + m0 + tx] = tl[kp][tx];
    }
}

__global__ __launch_bounds__(256)
void pack_w(const float* __restrict__ Wq, const float* __restrict__ Wk,
            const float* __restrict__ Wv, const float* __restrict__ Wo) {
    const int z = blockIdx.z;
    const float* W = (z == 0) ? Wq : (z == 1) ? Wk : (z == 2) ? Wv : Wo;
    const int n  = blockIdx.x * 256 + threadIdx.x;
    const int kp = blockIdx.y;
    uint32_t h, l;
    packpair_bf16(W[(size_t)(2 * kp) * N_ + n],
                  W[(size_t)(2 * kp + 1) * N_ + n], h, l);
    const size_t o = (size_t)z * KP_ * N_ + (size_t)kp * N_ + n;
    g_wh[o] = h;
    g_wl[o] = l;
}

// ---------------------------------------------------------------------------
// 3xBF16 GEMM, cp.async 4-stage pipeline, fused per-output epilogues.
// MODE 0: fp32 C (+bias). MODE 1: packed-K output. MODE 2: V^T output.
// ---------------------------------------------------------------------------
constexpr int SSTR   = 136;
constexpr int STAGES = 4;
constexpr int ST_U32 = 4 * 8 * SSTR;
constexpr int OFF_AL = 8 * SSTR;
constexpr int OFF_BH = 16 * SSTR;
constexpr int OFF_BL = 24 * SSTR;

__device__ __forceinline__ void tgemm_body(const uint32_t* __restrict__ Ah,
                                           const uint32_t* __restrict__ Al,
                                           const uint32_t* __restrict__ Bh,
                                           const uint32_t* __restrict__ Bl,
                                           float* __restrict__ C,
                                           const float* __restrict__ bias,
                                           int mode) {
    extern __shared__ uint32_t smp[];
    const uint32_t sb0 = smem_u32(smp);

    const int t    = threadIdx.x;
    const int lane = t & 31;
    const int wid  = t >> 5;
    const int wM   = wid & 1;
    const int wN   = wid >> 1;
    const int g    = lane >> 2;
    const int tg   = lane & 3;

    const int r0 = blockIdx.y * 128;
    const int c0 = blockIdx.x * 128;

    const int crow = t >> 5;
    const int cc4  = (t & 31) * 4;

    float acc[4][4][4];
#pragma unroll
    for (int i = 0; i < 4; ++i)
#pragma unroll
        for (int j = 0; j < 4; ++j)
#pragma unroll
            for (int r = 0; r < 4; ++r) acc[i][j][r] = 0.f;

    const int NT = K_ / 16;

    auto issue = [&](int kt, int buf) {
        const uint32_t db = sb0 + (uint32_t)(buf * ST_U32 + crow * SSTR + cc4) * 4u;
        const size_t kr = (size_t)(kt * 8 + crow);
        CP_ASYNC16(db,               Ah + kr * M_ + r0 + cc4);
        CP_ASYNC16(db + OFF_AL * 4u, Al + kr * M_ + r0 + cc4);
        CP_ASYNC16(db + OFF_BH * 4u, Bh + kr * N_ + c0 + cc4);
        CP_ASYNC16(db + OFF_BL * 4u, Bl + kr * N_ + c0 + cc4);
    };

#pragma unroll
    for (int s = 0; s < STAGES - 1; ++s) {
        issue(s, s);
        CP_COMMIT();
    }

    for (int kt = 0; kt < NT; ++kt) {
        CP_WAIT2();
        __syncthreads();

        const uint32_t* sA_hi = smp + (kt % STAGES) * ST_U32;
        const uint32_t* sA_lo = sA_hi + OFF_AL;
        const uint32_t* sB_hi = sA_hi + OFF_BH;
        const uint32_t* sB_lo = sA_hi + OFF_BL;

        uint32_t bh[4][2], bl[4][2];
#pragma unroll
        for (int nf = 0; nf < 4; ++nf) {
            const int cc = wN * 32 + nf * 8 + g;
            bh[nf][0] = sB_hi[tg * SSTR + cc];
            bh[nf][1] = sB_hi[(tg + 4) * SSTR + cc];
            bl[nf][0] = sB_lo[tg * SSTR + cc];
            bl[nf][1] = sB_lo[(tg + 4) * SSTR + cc];
        }
#pragma unroll
        for (int mf = 0; mf < 4; ++mf) {
            const int rb = wM * 64 + mf * 16 + g;
            uint32_t ah[4], al[4];
            ah[0] = sA_hi[tg * SSTR + rb];
            ah[1] = sA_hi[tg * SSTR + rb + 8];
            ah[2] = sA_hi[(tg + 4) * SSTR + rb];
            ah[3] = sA_hi[(tg + 4) * SSTR + rb + 8];
            al[0] = sA_lo[tg * SSTR + rb];
            al[1] = sA_lo[tg * SSTR + rb + 8];
            al[2] = sA_lo[(tg + 4) * SSTR + rb];
            al[3] = sA_lo[(tg + 4) * SSTR + rb + 8];
#pragma unroll
            for (int nf = 0; nf < 4; ++nf) {
                MMA_BF16(acc[mf][nf], al, bh[nf]);
                MMA_BF16(acc[mf][nf], ah, bl[nf]);
                MMA_BF16(acc[mf][nf], ah, bh[nf]);
            }
        }

        const int kn = kt + STAGES - 1;
        if (kn < NT) issue(kn, kn % STAGES);
        CP_COMMIT();
    }

    // Epilogue (per mode)
#pragma unroll
    for (int mf = 0; mf < 4; ++mf) {
#pragma unroll
        for (int nf = 0; nf < 4; ++nf) {
            const int row = r0 + wM * 64 + mf * 16 + g;
            const int col = c0 + wN * 32 + nf * 8 + 2 * tg;
            float2 v0 = make_float2(acc[mf][nf][0], acc[mf][nf][1]);
            float2 v1 = make_float2(acc[mf][nf][2], acc[mf][nf][3]);
            if (mode == 0) {
                if (bias) {
                    const float b0v = bias[col], b1v = bias[col + 1];
                    v0.x += b0v; v0.y += b1v;
                    v1.x += b0v; v1.y += b1v;
                }
                *reinterpret_cast<float2*>(&C[(size_t)row * N_ + col])       = v0;
                *reinterpret_cast<float2*>(&C[(size_t)(row + 8) * N_ + col]) = v1;
            } else if (mode == 1) {
                // K: packed bf16 hi/lo at [b*512 + col/2][t]
                const int b  = row >> 11;
                const int tt = row & (T_ - 1);
                const size_t ix = ((size_t)(b * 512 + (col >> 1))) * T_ + tt;
                uint32_t ph, pl;
                packpair_bf16(v0.x, v0.y, ph, pl);
                g_kh[ix] = ph; g_kl[ix] = pl;
                packpair_bf16(v1.x, v1.y, ph, pl);
                g_kh[ix + 8] = ph; g_kl[ix + 8] = pl;
            } else {
                // V: transposed rna-tf32 at [b*D + col][t]
                const int b  = row >> 11;
                const int tt = row & (T_ - 1);
                const size_t ix = ((size_t)b * D_ + col) * T_ + tt;
                g_vT[ix]          = rna_tf32(v0.x);
                g_vT[ix + T_]     = rna_tf32(v0.y);
                g_vT[ix + 8]      = rna_tf32(v1.x);
                g_vT[ix + T_ + 8] = rna_tf32(v1.y);
            }
        }
    }
}

__global__ __launch_bounds__(256, 2)
void tgemm_qkv() {
    const int z = blockIdx.z;
    tgemm_body(g_ah, g_al,
               g_wh + (size_t)z * KP_ * N_, g_wl + (size_t)z * KP_ * N_,
               (z == 0) ? g_q : nullptr, nullptr, z);
}

__global__ __launch_bounds__(256, 2)
void tgemm_out(const float* __restrict__ bo, float* __restrict__ out) {
    tgemm_body(g_ch, g_cl,
               g_wh + (size_t)3 * KP_ * N_, g_wl + (size_t)3 * KP_ * N_,
               out, bo, 0);
}

// ---------------------------------------------------------------------------
// Tensor-core causal flash attention.
// CTA: 256 threads (8 warps), 128 q-rows; KV tiles of 64, cp.async x2 stages.
// QK^T: 3xBF16 (K pre-packed). PV: tf32. ctx written packed bf16 hi/lo.
// ---------------------------------------------------------------------------
constexpr int FSTR = 68;   // fp32 row stride
constexpr int KSTR = 72;   // u32 row stride for K tiles
// smem word layout
constexpr int SM_QS  = 0;                        // 128*FSTR fp32
constexpr int SM_ST0 = 128 * FSTR;               // stage 0
constexpr int ST_WORDS = 2 * 32 * KSTR + 64 * FSTR;  // Kh + Kl + Vt = 8960
constexpr int OFF_KL2 = 32 * KSTR;
constexpr int OFF_VT2 = 64 * KSTR;
constexpr int SM_ATT = SM_ST0 + 2 * ST_WORDS;    // total words (26624)

__global__ __launch_bounds__(256, 1)
void flash_attn_tc() {
    extern __shared__ float sm[];
    float* Qs = sm + SM_QS;
    const uint32_t sb0 = smem_u32(sm);

    const int t    = threadIdx.x;
    const int lane = t & 31;
    const int w    = t >> 5;
    const int g    = lane >> 2;
    const int tg   = lane & 3;

    const int qb = (int)gridDim.x - 1 - (int)blockIdx.x;  // long blocks first
    const int hh = blockIdx.y;
    const int b  = blockIdx.z;
    const int q0 = qb * 128;
    const size_t qbase = (size_t)b * T_ * D_ + (size_t)hh * DH_;
    const size_t vtb   = (size_t)b * D_ * T_ + (size_t)hh * DH_ * T_;
    const size_t kbb   = ((size_t)b * 512 + hh * 32) * T_;

    const int ntiles = 2 * qb + 2;

    // cp.async stage loader: KV tile kt -> stage buf
    auto issue = [&](int kt, int buf) {
        const uint32_t st = sb0 + (uint32_t)(SM_ST0 + buf * ST_WORDS) * 4u;
        // K hi/lo: 32 rows x 64 u32
        for (int idx = t; idx < 512; idx += 256) {
            const int r = idx >> 4, c4 = (idx & 15) * 4;
            const size_t gk = kbb + (size_t)r * T_ + kt * 64 + c4;
            const uint32_t d = st + (uint32_t)(r * KSTR + c4) * 4u;
            CP_ASYNC16(d,                  g_kh + gk);
            CP_ASYNC16(d + OFF_KL2 * 4u,   g_kl + gk);
        }
        // V^T: 64 rows x 16 float4
        for (int idx = t; idx < 1024; idx += 256) {
            const int r = idx >> 4, c4 = (idx & 15) * 4;
            CP_ASYNC16(st + (uint32_t)(OFF_VT2 + r * FSTR + c4) * 4u,
                       g_vT + vtb + (size_t)r * T_ + kt * 64 + c4);
        }
    };

    // Kick stage 0 immediately (overlaps Q staging)
    issue(0, 0);
    CP_COMMIT();

    // Stage Q (scaled by 1/sqrt(64))
    for (int idx = t; idx < 128 * 16; idx += 256) {
        const int r = idx >> 4, c4 = (idx & 15) * 4;
        float4 v = *reinterpret_cast<const float4*>(
            &g_q[qbase + (size_t)(q0 + r) * D_ + c4]);
        v.x *= 0.125f; v.y *= 0.125f; v.z *= 0.125f; v.w *= 0.125f;
        *reinterpret_cast<float4*>(&Qs[r * FSTR + c4]) = v;
    }
    __syncthreads();

    // Q -> bf16 hi/lo k16 A-fragments
    const int r0 = w * 16 + g;
    const int r1 = r0 + 8;
    uint32_t qh[4][4], ql[4][4];
#pragma unroll
    for (int ks = 0; ks < 4; ++ks) {
        const int c = ks * 16 + 2 * tg;
        packpair_bf16(Qs[r0 * FSTR + c],     Qs[r0 * FSTR + c + 1],
                      qh[ks][0], ql[ks][0]);
        packpair_bf16(Qs[r1 * FSTR + c],     Qs[r1 * FSTR + c + 1],
                      qh[ks][1], ql[ks][1]);
        packpair_bf16(Qs[r0 * FSTR + c + 8], Qs[r0 * FSTR + c + 9],
                      qh[ks][2], ql[ks][2]);
        packpair_bf16(Qs[r1 * FSTR + c + 8], Qs[r1 * FSTR + c + 9],
                      qh[ks][3], ql[ks][3]);
    }

    float o[8][4];
#pragma unroll
    for (int nf = 0; nf < 8; ++nf)
#pragma unroll
        for (int r = 0; r < 4; ++r) o[nf][r] = 0.f;
    float m0 = -1e30f, m1 = -1e30f, l0 = 0.f, l1 = 0.f;

    for (int kt = 0; kt < ntiles; ++kt) {
        // Prefetch next tile, then wait for current
        if (kt + 1 < ntiles) {
            issue(kt + 1, (kt + 1) & 1);
            CP_COMMIT();
            CP_WAIT1();
        } else {
            CP_WAIT0();
        }
        __syncthreads();

        const float*    stf = sm + SM_ST0 + (kt & 1) * ST_WORDS;
        const uint32_t* Kh  = reinterpret_cast<const uint32_t*>(stf);
        const uint32_t* Kl  = Kh + OFF_KL2;
        const float*    Vt  = stf + OFF_VT2;

        // S = Q K^T (3xBF16)
        float s[8][4];
#pragma unroll
        for (int nf = 0; nf < 8; ++nf)
#pragma unroll
            for (int r = 0; r < 4; ++r) s[nf][r] = 0.f;

#pragma unroll
        for (int ks = 0; ks < 4; ++ks) {
#pragma unroll
            for (int nf = 0; nf < 8; ++nf) {
                const int cc = nf * 8 + g;
                uint32_t bh[2], bl[2];
                bh[0] = Kh[(ks * 8 + tg) * KSTR + cc];
                bh[1] = Kh[(ks * 8 + tg + 4) * KSTR + cc];
                bl[0] = Kl[(ks * 8 + tg) * KSTR + cc];
                bl[1] = Kl[(ks * 8 + tg + 4) * KSTR + cc];
                MMA_BF16(s[nf], ql[ks], bh);
                MMA_BF16(s[nf], qh[ks], bl);
                MMA_BF16(s[nf], qh[ks], bh);
            }
        }

        // Causal mask: kv_global = kt*64 + c; mask if c + off > r0 (off>=0
        // only for the last two tiles)
        const int off = kt * 64 - q0;
        if (off >= 0) {
#pragma unroll
            for (int nf = 0; nf < 8; ++nf) {
                const int c = nf * 8 + 2 * tg + off;
                if (c     > r0) s[nf][0] = -1e30f;
                if (c + 1 > r0) s[nf][1] = -1e30f;
                if (c     > r1) s[nf][2] = -1e30f;
                if (c + 1 > r1) s[nf][3] = -1e30f;
            }
        }

        // Online softmax
        float mx0 = -1e30f, mx1 = -1e30f;
#pragma unroll
        for (int nf = 0; nf < 8; ++nf) {
            mx0 = fmaxf(mx0, fmaxf(s[nf][0], s[nf][1]));
            mx1 = fmaxf(mx1, fmaxf(s[nf][2], s[nf][3]));
        }
        mx0 = fmaxf(mx0, __shfl_xor_sync(0xffffffffu, mx0, 1));
        mx0 = fmaxf(mx0, __shfl_xor_sync(0xffffffffu, mx0, 2));
        mx1 = fmaxf(mx1, __shfl_xor_sync(0xffffffffu, mx1, 1));
        mx1 = fmaxf(mx1, __shfl_xor_sync(0xffffffffu, mx1, 2));
        const float mn0 = fmaxf(m0, mx0);
        const float mn1 = fmaxf(m1, mx1);
        const float a0 = __expf(m0 - mn0);
        const float a1 = __expf(m1 - mn1);

        float rs0 = 0.f, rs1 = 0.f;
#pragma unroll
        for (int nf = 0; nf < 8; ++nf) {
            s[nf][0] = __expf(s[nf][0] - mn0); rs0 += s[nf][0];
            s[nf][1] = __expf(s[nf][1] - mn0); rs0 += s[nf][1];
            s[nf][2] = __expf(s[nf][2] - mn1); rs1 += s[nf][2];
            s[nf][3] = __expf(s[nf][3] - mn1); rs1 += s[nf][3];
            o[nf][0] *= a0; o[nf][1] *= a0;
            o[nf][2] *= a1; o[nf][3] *= a1;
        }
        rs0 += __shfl_xor_sync(0xffffffffu, rs0, 1);
        rs0 += __shfl_xor_sync(0xffffffffu, rs0, 2);
        rs1 += __shfl_xor_sync(0xffffffffu, rs1, 1);
        rs1 += __shfl_xor_sync(0xffffffffu, rs1, 2);
        l0 = l0 * a0 + rs0;
        l1 = l1 * a1 + rs1;
        m0 = mn0; m1 = mn1;

        // Stage P (rna tf32) in warp-private smem rows (Qs reuse)
        float* Ps = Qs;
#pragma unroll
        for (int nf = 0; nf < 8; ++nf) {
            const int c = nf * 8 + 2 * tg;
            Ps[r0 * FSTR + c]     = rna_tf32(s[nf][0]);
            Ps[r0 * FSTR + c + 1] = rna_tf32(s[nf][1]);
            Ps[r1 * FSTR + c]     = rna_tf32(s[nf][2]);
            Ps[r1 * FSTR + c + 1] = rna_tf32(s[nf][3]);
        }

        // O += P V (tf32)
#pragma unroll
        for (int k = 0; k < 8; ++k) {
            uint32_t pa[4];
            pa[0] = __float_as_uint(Ps[r0 * FSTR + k * 8 + tg]);
            pa[1] = __float_as_uint(Ps[r1 * FSTR + k * 8 + tg]);
            pa[2] = __float_as_uint(Ps[r0 * FSTR + k * 8 + tg + 4]);
            pa[3] = __float_as_uint(Ps[r1 * FSTR + k * 8 + tg + 4]);
#pragma unroll
            for (int nf = 0; nf < 8; ++nf) {
                uint32_t vb[2];
                vb[0] = __float_as_uint(Vt[(nf * 8 + g) * FSTR + k * 8 + tg]);
                vb[1] = __float_as_uint(Vt[(nf * 8 + g) * FSTR + k * 8 + tg + 4]);
                MMA_TF32(o[nf], pa, vb);
            }
        }
        __syncthreads();   // readers done before next issue reuses buffer
    }

    // Normalize + write ctx packed [D/2][M]
    const float i0 = 1.f / l0;
    const float i1 = 1.f / l1;
    const int mg = b * T_ + q0;
#pragma unroll
    for (int nf = 0; nf < 8; ++nf) {
        const int col = hh * DH_ + nf * 8 + 2 * tg;
        const size_t kp = (size_t)(col >> 1) * M_;
        uint32_t ph, pl;
        packpair_bf16(o[nf][0] * i0, o[nf][1] * i0, ph, pl);
        g_ch[kp + mg + r0] = ph;
        g_cl[kp + mg + r0] = pl;
        packpair_bf16(o[nf][2] * i1, o[nf][3] * i1, ph, pl);
        g_ch[kp + mg + r1] = ph;
        g_cl[kp + mg + r1] = pl;
    }
}

// ---------------------------------------------------------------------------
extern "C" void kernel_launch(void* const* d_in, const int* in_sizes, int n_in,
                              void* d_out, int out_size) {
    const float* x  = (const float*)d_in[0];
    const float* Wq = (const float*)d_in[1];
    const float* Wk = (const float*)d_in[2];
    const float* Wv = (const float*)d_in[3];
    const float* Wo = (const float*)d_in[4];
    const float* bo = (const float*)d_in[5];
    float* out = (float*)d_out;

    // 0) Pack x and weights
    pack_x<<<dim3(M_ / 32, KP_ / 32), dim3(32, 8)>>>(x);
    pack_w<<<dim3(N_ / 256, KP_, 4), 256>>>(Wq, Wk, Wv, Wo);

    const int gsmem = STAGES * ST_U32 * 4;
    cudaFuncSetAttribute(tgemm_qkv,
                         cudaFuncAttributeMaxDynamicSharedMemorySize, gsmem);
    cudaFuncSetAttribute(tgemm_out,
                         cudaFuncAttributeMaxDynamicSharedMemorySize, gsmem);

    // 1) QKV projections with fused K-pack / V-transpose epilogues
    tgemm_qkv<<<dim3(N_ / 128, M_ / 128, 3), 256, gsmem>>>();

    // 2) Attention (BQ=128, cp.async double-buffered; writes packed ctx)
    const int asmem = SM_ATT * sizeof(float);   // 106,496 B
    cudaFuncSetAttribute(flash_attn_tc,
                         cudaFuncAttributeMaxDynamicSharedMemorySize, asmem);
    flash_attn_tc<<<dim3(T_ / 128, H_, B_), 256, asmem>>>();

    // 3) Output projection (+bias)
    tgemm_out<<<dim3(N_ / 128, M_ / 128), 256, gsmem>>>(bo, out);
}

// round 8
// speedup vs baseline: 1.2335x; 1.0520x over previous
#include <cuda_runtime.h>
#include <cuda_bf16.h>
#include <math.h>
#include <stdint.h>

// Problem constants
constexpr int B_  = 4;
constexpr int T_  = 2048;
constexpr int D_  = 1024;
constexpr int H_  = 16;
constexpr int DH_ = 64;
constexpr int M_  = B_ * T_;   // 8192
constexpr int N_  = D_;        // 1024
constexpr int K_  = D_;        // 1024
constexpr int KP_ = K_ / 2;    // 512

// Scratch (device globals: allocation-free per harness rules).
__device__ float    g_q [M_ * D_];            // Q fp32 [B][T][D]
__device__ float    g_vT[M_ * D_];            // V^T tf32 [B][D][T]
__device__ uint32_t g_kh[KP_ * M_];           // K packed hi [B][512][T]
__device__ uint32_t g_kl[KP_ * M_];           // K packed lo
__device__ uint32_t g_ah[KP_ * M_];           // x packed hi  [K/2][M]
__device__ uint32_t g_al[KP_ * M_];           // x packed lo
__device__ uint32_t g_ch[KP_ * M_];           // ctx packed hi [D/2][M]
__device__ uint32_t g_cl[KP_ * M_];           // ctx packed lo
__device__ uint32_t g_wh[4 * KP_ * N_];       // weights packed hi [z][K/2][N]
__device__ uint32_t g_wl[4 * KP_ * N_];       // weights packed lo

// ---------------------------------------------------------------------------
// Helpers
// ---------------------------------------------------------------------------
#define MMA_TF32(d, a, b)                                                    \
    asm volatile(                                                            \
        "mma.sync.aligned.m16n8k8.row.col.f32.tf32.tf32.f32 "                \
        "{%0,%1,%2,%3}, {%4,%5,%6,%7}, {%8,%9}, {%0,%1,%2,%3};"              \
        : "+f"((d)[0]), "+f"((d)[1]), "+f"((d)[2]), "+f"((d)[3])             \
        : "r"((a)[0]), "r"((a)[1]), "r"((a)[2]), "r"((a)[3]),                \
          "r"((b)[0]), "r"((b)[1]))

#define MMA_BF16(d, a, b)                                                    \
    asm volatile(                                                            \
        "mma.sync.aligned.m16n8k16.row.col.f32.bf16.bf16.f32 "               \
        "{%0,%1,%2,%3}, {%4,%5,%6,%7}, {%8,%9}, {%0,%1,%2,%3};"              \
        : "+f"((d)[0]), "+f"((d)[1]), "+f"((d)[2]), "+f"((d)[3])             \
        : "r"((a)[0]), "r"((a)[1]), "r"((a)[2]), "r"((a)[3]),                \
          "r"((b)[0]), "r"((b)[1]))

#define CP_ASYNC16(dst, src)                                                 \
    asm volatile("cp.async.cg.shared.global [%0], [%1], 16;"                 \
                 :: "r"(dst), "l"(src))
#define CP_COMMIT()  asm volatile("cp.async.commit_group;")
#define CP_WAIT0()   asm volatile("cp.async.wait_group 0;")
#define CP_WAIT1()   asm volatile("cp.async.wait_group 1;")
#define CP_WAIT2()   asm volatile("cp.async.wait_group 2;")

__device__ __forceinline__ uint32_t smem_u32(const void* p) {
    return (uint32_t)__cvta_generic_to_shared(p);
}

__device__ __forceinline__ float ex2f(float x) {
    float y;
    asm("ex2.approx.ftz.f32 %0, %1;" : "=f"(y) : "f"(x));
    return y;
}

__device__ __forceinline__ float rna_tf32(float x) {
    uint32_t u = __float_as_uint(x);
    u = (u + 0x1000u) & 0xFFFFE000u;
    return __uint_as_float(u);
}

__device__ __forceinline__ void packpair_bf16(float a, float b,
                                              uint32_t& h, uint32_t& l) {
    const float ha = __bfloat162float(__float2bfloat16(a));
    const float hb = __bfloat162float(__float2bfloat16(b));
    __nv_bfloat162 H = __floats2bfloat162_rn(ha, hb);
    __nv_bfloat162 L = __floats2bfloat162_rn(a - ha, b - hb);
    h = *reinterpret_cast<uint32_t*>(&H);
    l = *reinterpret_cast<uint32_t*>(&L);
}

// ---------------------------------------------------------------------------
// Packing kernels (inputs only)
// ---------------------------------------------------------------------------
__global__ __launch_bounds__(256)
void pack_x(const float* __restrict__ x) {
    __shared__ uint32_t th[32][33], tl[32][33];
    const int m0  = blockIdx.x * 32;
    const int kp0 = blockIdx.y * 32;
    const int tx  = threadIdx.x;
    const int ty  = threadIdx.y;
#pragma unroll
    for (int i = 0; i < 4; ++i) {
        const int m = ty + i * 8;
        float2 v = *reinterpret_cast<const float2*>(
            &x[(size_t)(m0 + m) * K_ + (size_t)(kp0 + tx) * 2]);
        packpair_bf16(v.x, v.y, th[tx][m], tl[tx][m]);
    }
    __syncthreads();
#pragma unroll
    for (int i = 0; i < 4; ++i) {
        const int kp = ty + i * 8;
        g_ah[(size_t)(kp0 + kp) * M_ + m0 + tx] = th[kp][tx];
        g_al[(size_t)(kp0 + kp) * M_ + m0 + tx] = tl[kp][tx];
    }
}

__global__ __launch_bounds__(256)
void pack_w(const float* __restrict__ Wq, const float* __restrict__ Wk,
            const float* __restrict__ Wv, const float* __restrict__ Wo) {
    const int z = blockIdx.z;
    const float* W = (z == 0) ? Wq : (z == 1) ? Wk : (z == 2) ? Wv : Wo;
    const int n  = blockIdx.x * 256 + threadIdx.x;
    const int kp = blockIdx.y;
    uint32_t h, l;
    packpair_bf16(W[(size_t)(2 * kp) * N_ + n],
                  W[(size_t)(2 * kp + 1) * N_ + n], h, l);
    const size_t o = (size_t)z * KP_ * N_ + (size_t)kp * N_ + n;
    g_wh[o] = h;
    g_wl[o] = l;
}

// ---------------------------------------------------------------------------
// 3xBF16 GEMM, cp.async 4-stage pipeline, fused per-output epilogues.
// MODE 0: fp32 C (+bias). MODE 1: packed-K output. MODE 2: V^T output.
// ---------------------------------------------------------------------------
constexpr int SSTR   = 136;
constexpr int STAGES = 4;
constexpr int ST_U32 = 4 * 8 * SSTR;
constexpr int OFF_AL = 8 * SSTR;
constexpr int OFF_BH = 16 * SSTR;
constexpr int OFF_BL = 24 * SSTR;

__device__ __forceinline__ void tgemm_body(const uint32_t* __restrict__ Ah,
                                           const uint32_t* __restrict__ Al,
                                           const uint32_t* __restrict__ Bh,
                                           const uint32_t* __restrict__ Bl,
                                           float* __restrict__ C,
                                           const float* __restrict__ bias,
                                           int mode) {
    extern __shared__ uint32_t smp[];
    const uint32_t sb0 = smem_u32(smp);

    const int t    = threadIdx.x;
    const int lane = t & 31;
    const int wid  = t >> 5;
    const int wM   = wid & 1;
    const int wN   = wid >> 1;
    const int g    = lane >> 2;
    const int tg   = lane & 3;

    const int r0 = blockIdx.y * 128;
    const int c0 = blockIdx.x * 128;

    const int crow = t >> 5;
    const int cc4  = (t & 31) * 4;

    float acc[4][4][4];
#pragma unroll
    for (int i = 0; i < 4; ++i)
#pragma unroll
        for (int j = 0; j < 4; ++j)
#pragma unroll
            for (int r = 0; r < 4; ++r) acc[i][j][r] = 0.f;

    const int NT = K_ / 16;

    auto issue = [&](int kt, int buf) {
        const uint32_t db = sb0 + (uint32_t)(buf * ST_U32 + crow * SSTR + cc4) * 4u;
        const size_t kr = (size_t)(kt * 8 + crow);
        CP_ASYNC16(db,               Ah + kr * M_ + r0 + cc4);
        CP_ASYNC16(db + OFF_AL * 4u, Al + kr * M_ + r0 + cc4);
        CP_ASYNC16(db + OFF_BH * 4u, Bh + kr * N_ + c0 + cc4);
        CP_ASYNC16(db + OFF_BL * 4u, Bl + kr * N_ + c0 + cc4);
    };

#pragma unroll
    for (int s = 0; s < STAGES - 1; ++s) {
        issue(s, s);
        CP_COMMIT();
    }

    for (int kt = 0; kt < NT; ++kt) {
        CP_WAIT2();
        __syncthreads();

        const uint32_t* sA_hi = smp + (kt % STAGES) * ST_U32;
        const uint32_t* sA_lo = sA_hi + OFF_AL;
        const uint32_t* sB_hi = sA_hi + OFF_BH;
        const uint32_t* sB_lo = sA_hi + OFF_BL;

        uint32_t bh[4][2], bl[4][2];
#pragma unroll
        for (int nf = 0; nf < 4; ++nf) {
            const int cc = wN * 32 + nf * 8 + g;
            bh[nf][0] = sB_hi[tg * SSTR + cc];
            bh[nf][1] = sB_hi[(tg + 4) * SSTR + cc];
            bl[nf][0] = sB_lo[tg * SSTR + cc];
            bl[nf][1] = sB_lo[(tg + 4) * SSTR + cc];
        }
#pragma unroll
        for (int mf = 0; mf < 4; ++mf) {
            const int rb = wM * 64 + mf * 16 + g;
            uint32_t ah[4], al[4];
            ah[0] = sA_hi[tg * SSTR + rb];
            ah[1] = sA_hi[tg * SSTR + rb + 8];
            ah[2] = sA_hi[(tg + 4) * SSTR + rb];
            ah[3] = sA_hi[(tg + 4) * SSTR + rb + 8];
            al[0] = sA_lo[tg * SSTR + rb];
            al[1] = sA_lo[tg * SSTR + rb + 8];
            al[2] = sA_lo[(tg + 4) * SSTR + rb];
            al[3] = sA_lo[(tg + 4) * SSTR + rb + 8];
#pragma unroll
            for (int nf = 0; nf < 4; ++nf) {
                MMA_BF16(acc[mf][nf], al, bh[nf]);
                MMA_BF16(acc[mf][nf], ah, bl[nf]);
                MMA_BF16(acc[mf][nf], ah, bh[nf]);
            }
        }

        const int kn = kt + STAGES - 1;
        if (kn < NT) issue(kn, kn % STAGES);
        CP_COMMIT();
    }

    // Epilogue (per mode)
#pragma unroll
    for (int mf = 0; mf < 4; ++mf) {
#pragma unroll
        for (int nf = 0; nf < 4; ++nf) {
            const int row = r0 + wM * 64 + mf * 16 + g;
            const int col = c0 + wN * 32 + nf * 8 + 2 * tg;
            float2 v0 = make_float2(acc[mf][nf][0], acc[mf][nf][1]);
            float2 v1 = make_float2(acc[mf][nf][2], acc[mf][nf][3]);
            if (mode == 0) {
                if (bias) {
                    const float b0v = bias[col], b1v = bias[col + 1];
                    v0.x += b0v; v0.y += b1v;
                    v1.x += b0v; v1.y += b1v;
                }
                *reinterpret_cast<float2*>(&C[(size_t)row * N_ + col])       = v0;
                *reinterpret_cast<float2*>(&C[(size_t)(row + 8) * N_ + col]) = v1;
            } else if (mode == 1) {
                const int b  = row >> 11;
                const int tt = row & (T_ - 1);
                const size_t ix = ((size_t)(b * 512 + (col >> 1))) * T_ + tt;
                uint32_t ph, pl;
                packpair_bf16(v0.x, v0.y, ph, pl);
                g_kh[ix] = ph; g_kl[ix] = pl;
                packpair_bf16(v1.x, v1.y, ph, pl);
                g_kh[ix + 8] = ph; g_kl[ix + 8] = pl;
            } else {
                const int b  = row >> 11;
                const int tt = row & (T_ - 1);
                const size_t ix = ((size_t)b * D_ + col) * T_ + tt;
                g_vT[ix]          = rna_tf32(v0.x);
                g_vT[ix + T_]     = rna_tf32(v0.y);
                g_vT[ix + 8]      = rna_tf32(v1.x);
                g_vT[ix + T_ + 8] = rna_tf32(v1.y);
            }
        }
    }
}

__global__ __launch_bounds__(256, 2)
void tgemm_qkv() {
    const int z = blockIdx.z;
    tgemm_body(g_ah, g_al,
               g_wh + (size_t)z * KP_ * N_, g_wl + (size_t)z * KP_ * N_,
               (z == 0) ? g_q : nullptr, nullptr, z);
}

__global__ __launch_bounds__(256, 2)
void tgemm_out(const float* __restrict__ bo, float* __restrict__ out) {
    tgemm_body(g_ch, g_cl,
               g_wh + (size_t)3 * KP_ * N_, g_wl + (size_t)3 * KP_ * N_,
               out, bo, 0);
}

// ---------------------------------------------------------------------------
// Tensor-core causal flash attention.
// 256 thr (8 warps), 128 q-rows, KV tiles 64, cp.async x2.
// QK^T 3xBF16; softmax in log2 domain (ex2); P transposed C->A frag via
// register shuffles (no smem round-trip); PV tf32.
// Q staging overlaid on stage-1 buffer; smem 71.7KB -> 2 CTAs/SM.
// ---------------------------------------------------------------------------
constexpr int FSTR = 68;   // fp32 row stride (Vt / Q staging)
constexpr int KSTR = 72;   // u32 row stride for K tiles
constexpr int ST_WORDS = 2 * 32 * KSTR + 64 * FSTR;  // 8960 words / stage
constexpr int OFF_KL2 = 32 * KSTR;
constexpr int OFF_VT2 = 64 * KSTR;
constexpr int SM_ATT  = 2 * ST_WORDS;                // 17920 words = 71,680B

__global__ __launch_bounds__(256, 2)
void flash_attn_tc() {
    extern __shared__ float sm[];
    const uint32_t sb0 = smem_u32(sm);

    const int t    = threadIdx.x;
    const int lane = t & 31;
    const int w    = t >> 5;
    const int g    = lane >> 2;
    const int tg   = lane & 3;

    const int qb = (int)gridDim.x - 1 - (int)blockIdx.x;  // long blocks first
    const int hh = blockIdx.y;
    const int b  = blockIdx.z;
    const int q0 = qb * 128;
    const size_t qbase = (size_t)b * T_ * D_ + (size_t)hh * DH_;
    const size_t vtb   = (size_t)b * D_ * T_ + (size_t)hh * DH_ * T_;
    const size_t kbb   = ((size_t)b * 512 + hh * 32) * T_;

    const int ntiles = 2 * qb + 2;

    auto issue = [&](int kt, int buf) {
        const uint32_t st = sb0 + (uint32_t)(buf * ST_WORDS) * 4u;
        for (int idx = t; idx < 512; idx += 256) {
            const int r = idx >> 4, c4 = (idx & 15) * 4;
            const size_t gk = kbb + (size_t)r * T_ + kt * 64 + c4;
            const uint32_t d = st + (uint32_t)(r * KSTR + c4) * 4u;
            CP_ASYNC16(d,                g_kh + gk);
            CP_ASYNC16(d + OFF_KL2 * 4u, g_kl + gk);
        }
        for (int idx = t; idx < 1024; idx += 256) {
            const int r = idx >> 4, c4 = (idx & 15) * 4;
            CP_ASYNC16(st + (uint32_t)(OFF_VT2 + r * FSTR + c4) * 4u,
                       g_vT + vtb + (size_t)r * T_ + kt * 64 + c4);
        }
    };

    // Kick stage 0 (overlaps Q staging into the stage-1 region)
    issue(0, 0);
    CP_COMMIT();

    // Stage Q into stage-1 buffer region; prescale folds 1/sqrt(64) * log2(e)
    float* Qs = sm + ST_WORDS;
    const float qscale = 0.18033688011112042f;   // 0.125 * log2(e)
    for (int idx = t; idx < 128 * 16; idx += 256) {
        const int r = idx >> 4, c4 = (idx & 15) * 4;
        float4 v = *reinterpret_cast<const float4*>(
            &g_q[qbase + (size_t)(q0 + r) * D_ + c4]);
        v.x *= qscale; v.y *= qscale; v.z *= qscale; v.w *= qscale;
        *reinterpret_cast<float4*>(&Qs[r * FSTR + c4]) = v;
    }
    __syncthreads();

    // Q -> bf16 hi/lo k16 A-fragments
    const int r0 = w * 16 + g;
    const int r1 = r0 + 8;
    uint32_t qh[4][4], ql[4][4];
#pragma unroll
    for (int ks = 0; ks < 4; ++ks) {
        const int c = ks * 16 + 2 * tg;
        packpair_bf16(Qs[r0 * FSTR + c],     Qs[r0 * FSTR + c + 1],
                      qh[ks][0], ql[ks][0]);
        packpair_bf16(Qs[r1 * FSTR + c],     Qs[r1 * FSTR + c + 1],
                      qh[ks][1], ql[ks][1]);
        packpair_bf16(Qs[r0 * FSTR + c + 8], Qs[r0 * FSTR + c + 9],
                      qh[ks][2], ql[ks][2]);
        packpair_bf16(Qs[r1 * FSTR + c + 8], Qs[r1 * FSTR + c + 9],
                      qh[ks][3], ql[ks][3]);
    }
    __syncthreads();   // all frags extracted before stage-1 gets overwritten

    float o[8][4];
#pragma unroll
    for (int nf = 0; nf < 8; ++nf)
#pragma unroll
        for (int r = 0; r < 4; ++r) o[nf][r] = 0.f;
    float m0 = -1e30f, m1 = -1e30f, l0 = 0.f, l1 = 0.f;

    for (int kt = 0; kt < ntiles; ++kt) {
        if (kt + 1 < ntiles) {
            issue(kt + 1, (kt + 1) & 1);
            CP_COMMIT();
            CP_WAIT1();
        } else {
            CP_WAIT0();
        }
        __syncthreads();

        const float*    stf = sm + (kt & 1) * ST_WORDS;
        const uint32_t* Kh  = reinterpret_cast<const uint32_t*>(stf);
        const uint32_t* Kl  = Kh + OFF_KL2;
        const float*    Vt  = stf + OFF_VT2;

        // S = Q K^T (3xBF16); scores are in log2 domain
        float s[8][4];
#pragma unroll
        for (int nf = 0; nf < 8; ++nf)
#pragma unroll
            for (int r = 0; r < 4; ++r) s[nf][r] = 0.f;

#pragma unroll
        for (int ks = 0; ks < 4; ++ks) {
#pragma unroll
            for (int nf = 0; nf < 8; ++nf) {
                const int cc = nf * 8 + g;
                uint32_t bh[2], bl[2];
                bh[0] = Kh[(ks * 8 + tg) * KSTR + cc];
                bh[1] = Kh[(ks * 8 + tg + 4) * KSTR + cc];
                bl[0] = Kl[(ks * 8 + tg) * KSTR + cc];
                bl[1] = Kl[(ks * 8 + tg + 4) * KSTR + cc];
                MMA_BF16(s[nf], ql[ks], bh);
                MMA_BF16(s[nf], qh[ks], bl);
                MMA_BF16(s[nf], qh[ks], bh);
            }
        }

        // Causal mask (only the last two tiles of each block have off >= 0)
        const int off = kt * 64 - q0;
        if (off >= 0) {
#pragma unroll
            for (int nf = 0; nf < 8; ++nf) {
                const int c = nf * 8 + 2 * tg + off;
                if (c     > r0) s[nf][0] = -1e30f;
                if (c + 1 > r0) s[nf][1] = -1e30f;
                if (c     > r1) s[nf][2] = -1e30f;
                if (c + 1 > r1) s[nf][3] = -1e30f;
            }
        }

        // Online softmax (base-2)
        float mx0 = -1e30f, mx1 = -1e30f;
#pragma unroll
        for (int nf = 0; nf < 8; ++nf) {
            mx0 = fmaxf(mx0, fmaxf(s[nf][0], s[nf][1]));
            mx1 = fmaxf(mx1, fmaxf(s[nf][2], s[nf][3]));
        }
        mx0 = fmaxf(mx0, __shfl_xor_sync(0xffffffffu, mx0, 1));
        mx0 = fmaxf(mx0, __shfl_xor_sync(0xffffffffu, mx0, 2));
        mx1 = fmaxf(mx1, __shfl_xor_sync(0xffffffffu, mx1, 1));
        mx1 = fmaxf(mx1, __shfl_xor_sync(0xffffffffu, mx1, 2));
        const float mn0 = fmaxf(m0, mx0);
        const float mn1 = fmaxf(m1, mx1);
        const float a0 = ex2f(m0 - mn0);
        const float a1 = ex2f(m1 - mn1);

        float rs0 = 0.f, rs1 = 0.f;
#pragma unroll
        for (int nf = 0; nf < 8; ++nf) {
            s[nf][0] = ex2f(s[nf][0] - mn0); rs0 += s[nf][0];
            s[nf][1] = ex2f(s[nf][1] - mn0); rs0 += s[nf][1];
            s[nf][2] = ex2f(s[nf][2] - mn1); rs1 += s[nf][2];
            s[nf][3] = ex2f(s[nf][3] - mn1); rs1 += s[nf][3];
            o[nf][0] *= a0; o[nf][1] *= a0;
            o[nf][2] *= a1; o[nf][3] *= a1;
        }
        rs0 += __shfl_xor_sync(0xffffffffu, rs0, 1);
        rs0 += __shfl_xor_sync(0xffffffffu, rs0, 2);
        rs1 += __shfl_xor_sync(0xffffffffu, rs1, 1);
        rs1 += __shfl_xor_sync(0xffffffffu, rs1, 2);
        l0 = l0 * a0 + rs0;
        l1 = l1 * a1 + rs1;
        m0 = mn0; m1 = mn1;

        // O += P V: transpose C-frag -> A-frag via shuffles, then tf32 MMAs
        const int src0 = (lane & ~3) | (tg >> 1);
        const int src1 = src0 + 2;
        const bool odd = (tg & 1);
#pragma unroll
        for (int k = 0; k < 8; ++k) {
            uint32_t pa[4];
            float e, d;
            e = __shfl_sync(0xffffffffu, s[k][0], src0);
            d = __shfl_sync(0xffffffffu, s[k][1], src0);
            pa[0] = __float_as_uint(rna_tf32(odd ? d : e));
            e = __shfl_sync(0xffffffffu, s[k][2], src0);
            d = __shfl_sync(0xffffffffu, s[k][3], src0);
            pa[1] = __float_as_uint(rna_tf32(odd ? d : e));
            e = __shfl_sync(0xffffffffu, s[k][0], src1);
            d = __shfl_sync(0xffffffffu, s[k][1], src1);
            pa[2] = __float_as_uint(rna_tf32(odd ? d : e));
            e = __shfl_sync(0xffffffffu, s[k][2], src1);
            d = __shfl_sync(0xffffffffu, s[k][3], src1);
            pa[3] = __float_as_uint(rna_tf32(odd ? d : e));
#pragma unroll
            for (int nf = 0; nf < 8; ++nf) {
                uint32_t vb[2];
                vb[0] = __float_as_uint(Vt[(nf * 8 + g) * FSTR + k * 8 + tg]);
                vb[1] = __float_as_uint(Vt[(nf * 8 + g) * FSTR + k * 8 + tg + 4]);
                MMA_TF32(o[nf], pa, vb);
            }
        }
        __syncthreads();   // readers done before next issue reuses buffer
    }

    // Normalize + write ctx packed [D/2][M]
    const float i0 = 1.f / l0;
    const float i1 = 1.f / l1;
    const int mg = b * T_ + q0;
#pragma unroll
    for (int nf = 0; nf < 8; ++nf) {
        const int col = hh * DH_ + nf * 8 + 2 * tg;
        const size_t kp = (size_t)(col >> 1) * M_;
        uint32_t ph, pl;
        packpair_bf16(o[nf][0] * i0, o[nf][1] * i0, ph, pl);
        g_ch[kp + mg + r0] = ph;
        g_cl[kp + mg + r0] = pl;
        packpair_bf16(o[nf][2] * i1, o[nf][3] * i1, ph, pl);
        g_ch[kp + mg + r1] = ph;
        g_cl[kp + mg + r1] = pl;
    }
}

// ---------------------------------------------------------------------------
extern "C" void kernel_launch(void* const* d_in, const int* in_sizes, int n_in,
                              void* d_out, int out_size) {
    const float* x  = (const float*)d_in[0];
    const float* Wq = (const float*)d_in[1];
    const float* Wk = (const float*)d_in[2];
    const float* Wv = (const float*)d_in[3];
    const float* Wo = (const float*)d_in[4];
    const float* bo = (const float*)d_in[5];
    float* out = (float*)d_out;

    // 0) Pack x and weights
    pack_x<<<dim3(M_ / 32, KP_ / 32), dim3(32, 8)>>>(x);
    pack_w<<<dim3(N_ / 256, KP_, 4), 256>>>(Wq, Wk, Wv, Wo);

    const int gsmem = STAGES * ST_U32 * 4;
    cudaFuncSetAttribute(tgemm_qkv,
                         cudaFuncAttributeMaxDynamicSharedMemorySize, gsmem);
    cudaFuncSetAttribute(tgemm_out,
                         cudaFuncAttributeMaxDynamicSharedMemorySize, gsmem);

    // 1) QKV projections with fused K-pack / V-transpose epilogues
    tgemm_qkv<<<dim3(N_ / 128, M_ / 128, 3), 256, gsmem>>>();

    // 2) Attention (writes packed ctx)
    const int asmem = SM_ATT * sizeof(float);   // 71,680 B
    cudaFuncSetAttribute(flash_attn_tc,
                         cudaFuncAttributeMaxDynamicSharedMemorySize, asmem);
    flash_attn_tc<<<dim3(T_ / 128, H_, B_), 256, asmem>>>();

    // 3) Output projection (+bias)
    tgemm_out<<<dim3(N_ / 128, M_ / 128), 256, gsmem>>>(bo, out);
}

// round 9
// speedup vs baseline: 1.2710x; 1.0304x over previous
#include <cuda_runtime.h>
#include <cuda_bf16.h>
#include <math.h>
#include <stdint.h>

// Problem constants
constexpr int B_  = 4;
constexpr int T_  = 2048;
constexpr int D_  = 1024;
constexpr int H_  = 16;
constexpr int DH_ = 64;
constexpr int M_  = B_ * T_;   // 8192
constexpr int N_  = D_;        // 1024
constexpr int K_  = D_;        // 1024
constexpr int KP_ = K_ / 2;    // 512

// Scratch (device globals: allocation-free per harness rules).
__device__ float    g_q [M_ * D_];            // Q fp32 [B][T][D]
__device__ float    g_vT[M_ * D_];            // V^T tf32 [B][D][T]
__device__ uint32_t g_kh[KP_ * M_];           // K packed hi [B][512][T]
__device__ uint32_t g_kl[KP_ * M_];           // K packed lo
__device__ uint32_t g_ah[KP_ * M_];           // x packed hi  [K/2][M]
__device__ uint32_t g_al[KP_ * M_];           // x packed lo
__device__ uint32_t g_ch[KP_ * M_];           // ctx packed hi [D/2][M]
__device__ uint32_t g_cl[KP_ * M_];           // ctx packed lo
__device__ uint32_t g_wh[4 * KP_ * N_];       // weights packed hi [z][K/2][N]
__device__ uint32_t g_wl[4 * KP_ * N_];       // weights packed lo

// ---------------------------------------------------------------------------
// Helpers
// ---------------------------------------------------------------------------
#define MMA_TF32(d, a, b)                                                    \
    asm volatile(                                                            \
        "mma.sync.aligned.m16n8k8.row.col.f32.tf32.tf32.f32 "                \
        "{%0,%1,%2,%3}, {%4,%5,%6,%7}, {%8,%9}, {%0,%1,%2,%3};"              \
        : "+f"((d)[0]), "+f"((d)[1]), "+f"((d)[2]), "+f"((d)[3])             \
        : "r"((a)[0]), "r"((a)[1]), "r"((a)[2]), "r"((a)[3]),                \
          "r"((b)[0]), "r"((b)[1]))

#define MMA_BF16(d, a, b)                                                    \
    asm volatile(                                                            \
        "mma.sync.aligned.m16n8k16.row.col.f32.bf16.bf16.f32 "               \
        "{%0,%1,%2,%3}, {%4,%5,%6,%7}, {%8,%9}, {%0,%1,%2,%3};"              \
        : "+f"((d)[0]), "+f"((d)[1]), "+f"((d)[2]), "+f"((d)[3])             \
        : "r"((a)[0]), "r"((a)[1]), "r"((a)[2]), "r"((a)[3]),                \
          "r"((b)[0]), "r"((b)[1]))

#define CP_ASYNC16(dst, src)                                                 \
    asm volatile("cp.async.cg.shared.global [%0], [%1], 16;"                 \
                 :: "r"(dst), "l"(src))
#define CP_COMMIT()  asm volatile("cp.async.commit_group;")
#define CP_WAIT0()   asm volatile("cp.async.wait_group 0;")
#define CP_WAIT1()   asm volatile("cp.async.wait_group 1;")
#define CP_WAIT2()   asm volatile("cp.async.wait_group 2;")

__device__ __forceinline__ uint32_t smem_u32(const void* p) {
    return (uint32_t)__cvta_generic_to_shared(p);
}

__device__ __forceinline__ float ex2f(float x) {
    float y;
    asm("ex2.approx.ftz.f32 %0, %1;" : "=f"(y) : "f"(x));
    return y;
}

__device__ __forceinline__ float rna_tf32(float x) {
    uint32_t u = __float_as_uint(x);
    u = (u + 0x1000u) & 0xFFFFE000u;
    return __uint_as_float(u);
}

__device__ __forceinline__ void packpair_bf16(float a, float b,
                                              uint32_t& h, uint32_t& l) {
    const float ha = __bfloat162float(__float2bfloat16(a));
    const float hb = __bfloat162float(__float2bfloat16(b));
    __nv_bfloat162 H = __floats2bfloat162_rn(ha, hb);
    __nv_bfloat162 L = __floats2bfloat162_rn(a - ha, b - hb);
    h = *reinterpret_cast<uint32_t*>(&H);
    l = *reinterpret_cast<uint32_t*>(&L);
}

// ---------------------------------------------------------------------------
// Packing kernels (inputs only)
// ---------------------------------------------------------------------------
__global__ __launch_bounds__(256)
void pack_x(const float* __restrict__ x) {
    __shared__ uint32_t th[32][33], tl[32][33];
    const int m0  = blockIdx.x * 32;
    const int kp0 = blockIdx.y * 32;
    const int tx  = threadIdx.x;
    const int ty  = threadIdx.y;
#pragma unroll
    for (int i = 0; i < 4; ++i) {
        const int m = ty + i * 8;
        float2 v = *reinterpret_cast<const float2*>(
            &x[(size_t)(m0 + m) * K_ + (size_t)(kp0 + tx) * 2]);
        packpair_bf16(v.x, v.y, th[tx][m], tl[tx][m]);
    }
    __syncthreads();
#pragma unroll
    for (int i = 0; i < 4; ++i) {
        const int kp = ty + i * 8;
        g_ah[(size_t)(kp0 + kp) * M_ + m0 + tx] = th[kp][tx];
        g_al[(size_t)(kp0 + kp) * M_ + m0 + tx] = tl[kp][tx];
    }
}

__global__ __launch_bounds__(256)
void pack_w(const float* __restrict__ Wq, const float* __restrict__ Wk,
            const float* __restrict__ Wv, const float* __restrict__ Wo) {
    const int z = blockIdx.z;
    const float* W = (z == 0) ? Wq : (z == 1) ? Wk : (z == 2) ? Wv : Wo;
    const int n  = blockIdx.x * 256 + threadIdx.x;
    const int kp = blockIdx.y;
    uint32_t h, l;
    packpair_bf16(W[(size_t)(2 * kp) * N_ + n],
                  W[(size_t)(2 * kp + 1) * N_ + n], h, l);
    const size_t o = (size_t)z * KP_ * N_ + (size_t)kp * N_ + n;
    g_wh[o] = h;
    g_wl[o] = l;
}

// ---------------------------------------------------------------------------
// 3xBF16 GEMM, cp.async 4-stage pipeline, fused per-output epilogues.
// MODE 0: fp32 C (+bias). MODE 1: packed-K output. MODE 2: V^T output.
// ---------------------------------------------------------------------------
constexpr int SSTR   = 136;
constexpr int STAGES = 4;
constexpr int ST_U32 = 4 * 8 * SSTR;
constexpr int OFF_AL = 8 * SSTR;
constexpr int OFF_BH = 16 * SSTR;
constexpr int OFF_BL = 24 * SSTR;

__device__ __forceinline__ void tgemm_body(const uint32_t* __restrict__ Ah,
                                           const uint32_t* __restrict__ Al,
                                           const uint32_t* __restrict__ Bh,
                                           const uint32_t* __restrict__ Bl,
                                           float* __restrict__ C,
                                           const float* __restrict__ bias,
                                           int mode) {
    extern __shared__ uint32_t smp[];
    const uint32_t sb0 = smem_u32(smp);

    const int t    = threadIdx.x;
    const int lane = t & 31;
    const int wid  = t >> 5;
    const int wM   = wid & 1;
    const int wN   = wid >> 1;
    const int g    = lane >> 2;
    const int tg   = lane & 3;

    const int r0 = blockIdx.y * 128;
    const int c0 = blockIdx.x * 128;

    const int crow = t >> 5;
    const int cc4  = (t & 31) * 4;

    float acc[4][4][4];
#pragma unroll
    for (int i = 0; i < 4; ++i)
#pragma unroll
        for (int j = 0; j < 4; ++j)
#pragma unroll
            for (int r = 0; r < 4; ++r) acc[i][j][r] = 0.f;

    const int NT = K_ / 16;

    auto issue = [&](int kt, int buf) {
        const uint32_t db = sb0 + (uint32_t)(buf * ST_U32 + crow * SSTR + cc4) * 4u;
        const size_t kr = (size_t)(kt * 8 + crow);
        CP_ASYNC16(db,               Ah + kr * M_ + r0 + cc4);
        CP_ASYNC16(db + OFF_AL * 4u, Al + kr * M_ + r0 + cc4);
        CP_ASYNC16(db + OFF_BH * 4u, Bh + kr * N_ + c0 + cc4);
        CP_ASYNC16(db + OFF_BL * 4u, Bl + kr * N_ + c0 + cc4);
    };

#pragma unroll
    for (int s = 0; s < STAGES - 1; ++s) {
        issue(s, s);
        CP_COMMIT();
    }

    for (int kt = 0; kt < NT; ++kt) {
        CP_WAIT2();
        __syncthreads();

        const uint32_t* sA_hi = smp + (kt % STAGES) * ST_U32;
        const uint32_t* sA_lo = sA_hi + OFF_AL;
        const uint32_t* sB_hi = sA_hi + OFF_BH;
        const uint32_t* sB_lo = sA_hi + OFF_BL;

        uint32_t bh[4][2], bl[4][2];
#pragma unroll
        for (int nf = 0; nf < 4; ++nf) {
            const int cc = wN * 32 + nf * 8 + g;
            bh[nf][0] = sB_hi[tg * SSTR + cc];
            bh[nf][1] = sB_hi[(tg + 4) * SSTR + cc];
            bl[nf][0] = sB_lo[tg * SSTR + cc];
            bl[nf][1] = sB_lo[(tg + 4) * SSTR + cc];
        }
#pragma unroll
        for (int mf = 0; mf < 4; ++mf) {
            const int rb = wM * 64 + mf * 16 + g;
            uint32_t ah[4], al[4];
            ah[0] = sA_hi[tg * SSTR + rb];
            ah[1] = sA_hi[tg * SSTR + rb + 8];
            ah[2] = sA_hi[(tg + 4) * SSTR + rb];
            ah[3] = sA_hi[(tg + 4) * SSTR + rb + 8];
            al[0] = sA_lo[tg * SSTR + rb];
            al[1] = sA_lo[tg * SSTR + rb + 8];
            al[2] = sA_lo[(tg + 4) * SSTR + rb];
            al[3] = sA_lo[(tg + 4) * SSTR + rb + 8];
#pragma unroll
            for (int nf = 0; nf < 4; ++nf) {
                MMA_BF16(acc[mf][nf], al, bh[nf]);
                MMA_BF16(acc[mf][nf], ah, bl[nf]);
                MMA_BF16(acc[mf][nf], ah, bh[nf]);
            }
        }

        const int kn = kt + STAGES - 1;
        if (kn < NT) issue(kn, kn % STAGES);
        CP_COMMIT();
    }

    // Epilogue (per mode)
#pragma unroll
    for (int mf = 0; mf < 4; ++mf) {
#pragma unroll
        for (int nf = 0; nf < 4; ++nf) {
            const int row = r0 + wM * 64 + mf * 16 + g;
            const int col = c0 + wN * 32 + nf * 8 + 2 * tg;
            float2 v0 = make_float2(acc[mf][nf][0], acc[mf][nf][1]);
            float2 v1 = make_float2(acc[mf][nf][2], acc[mf][nf][3]);
            if (mode == 0) {
                if (bias) {
                    const float b0v = bias[col], b1v = bias[col + 1];
                    v0.x += b0v; v0.y += b1v;
                    v1.x += b0v; v1.y += b1v;
                }
                *reinterpret_cast<float2*>(&C[(size_t)row * N_ + col])       = v0;
                *reinterpret_cast<float2*>(&C[(size_t)(row + 8) * N_ + col]) = v1;
            } else if (mode == 1) {
                const int b  = row >> 11;
                const int tt = row & (T_ - 1);
                const size_t ix = ((size_t)(b * 512 + (col >> 1))) * T_ + tt;
                uint32_t ph, pl;
                packpair_bf16(v0.x, v0.y, ph, pl);
                g_kh[ix] = ph; g_kl[ix] = pl;
                packpair_bf16(v1.x, v1.y, ph, pl);
                g_kh[ix + 8] = ph; g_kl[ix + 8] = pl;
            } else {
                const int b  = row >> 11;
                const int tt = row & (T_ - 1);
                const size_t ix = ((size_t)b * D_ + col) * T_ + tt;
                g_vT[ix]          = rna_tf32(v0.x);
                g_vT[ix + T_]     = rna_tf32(v0.y);
                g_vT[ix + 8]      = rna_tf32(v1.x);
                g_vT[ix + T_ + 8] = rna_tf32(v1.y);
            }
        }
    }
}

__global__ __launch_bounds__(256, 2)
void tgemm_qkv() {
    const int z = blockIdx.z;
    tgemm_body(g_ah, g_al,
               g_wh + (size_t)z * KP_ * N_, g_wl + (size_t)z * KP_ * N_,
               (z == 0) ? g_q : nullptr, nullptr, z);
}

__global__ __launch_bounds__(256, 2)
void tgemm_out(const float* __restrict__ bo, float* __restrict__ out) {
    tgemm_body(g_ch, g_cl,
               g_wh + (size_t)3 * KP_ * N_, g_wl + (size_t)3 * KP_ * N_,
               out, bo, 0);
}

// ---------------------------------------------------------------------------
// Tensor-core causal flash attention, mf=2.
// 128 thr (4 warps), each warp owns 32 q-rows (two m16 frags) -> every K/V
// smem fragment read feeds TWO MMAs (halves smem traffic per q-row).
// QK^T 3xBF16, softmax base-2 (ex2), P transposed via shuffles, PV tf32.
// ---------------------------------------------------------------------------
constexpr int FSTR = 68;   // fp32 row stride (Vt / Q staging)
constexpr int KSTR = 72;   // u32 row stride for K tiles
constexpr int ST_WORDS = 2 * 32 * KSTR + 64 * FSTR;  // 8960 words / stage
constexpr int OFF_KL2 = 32 * KSTR;
constexpr int OFF_VT2 = 64 * KSTR;
constexpr int SM_ATT  = 2 * ST_WORDS;                // 71,680 B

__global__ __launch_bounds__(128, 2)
void flash_attn_tc() {
    extern __shared__ float sm[];
    const uint32_t sb0 = smem_u32(sm);

    const int t    = threadIdx.x;
    const int lane = t & 31;
    const int w    = t >> 5;          // 0..3
    const int g    = lane >> 2;
    const int tg   = lane & 3;

    const int qb = (int)gridDim.x - 1 - (int)blockIdx.x;  // long blocks first
    const int hh = blockIdx.y;
    const int b  = blockIdx.z;
    const int q0 = qb * 128;
    const size_t qbase = (size_t)b * T_ * D_ + (size_t)hh * DH_;
    const size_t vtb   = (size_t)b * D_ * T_ + (size_t)hh * DH_ * T_;
    const size_t kbb   = ((size_t)b * 512 + hh * 32) * T_;

    const int ntiles = 2 * qb + 2;

    auto issue = [&](int kt, int buf) {
        const uint32_t st = sb0 + (uint32_t)(buf * ST_WORDS) * 4u;
        for (int idx = t; idx < 512; idx += 128) {
            const int r = idx >> 4, c4 = (idx & 15) * 4;
            const size_t gk = kbb + (size_t)r * T_ + kt * 64 + c4;
            const uint32_t d = st + (uint32_t)(r * KSTR + c4) * 4u;
            CP_ASYNC16(d,                g_kh + gk);
            CP_ASYNC16(d + OFF_KL2 * 4u, g_kl + gk);
        }
        for (int idx = t; idx < 1024; idx += 128) {
            const int r = idx >> 4, c4 = (idx & 15) * 4;
            CP_ASYNC16(st + (uint32_t)(OFF_VT2 + r * FSTR + c4) * 4u,
                       g_vT + vtb + (size_t)r * T_ + kt * 64 + c4);
        }
    };

    // Kick stage 0 (overlaps Q staging into the stage-1 region)
    issue(0, 0);
    CP_COMMIT();

    // Stage Q into stage-1 buffer region; prescale folds 1/sqrt(64) * log2(e)
    float* Qs = sm + ST_WORDS;
    const float qscale = 0.18033688011112042f;   // 0.125 * log2(e)
    for (int idx = t; idx < 128 * 16; idx += 128) {
        const int r = idx >> 4, c4 = (idx & 15) * 4;
        float4 v = *reinterpret_cast<const float4*>(
            &g_q[qbase + (size_t)(q0 + r) * D_ + c4]);
        v.x *= qscale; v.y *= qscale; v.z *= qscale; v.w *= qscale;
        *reinterpret_cast<float4*>(&Qs[r * FSTR + c4]) = v;
    }
    __syncthreads();

    // Q -> bf16 hi/lo k16 A-fragments, two m-frags per warp
    const int rb = w * 32;
    uint32_t qh[2][4][4], ql[2][4][4];
#pragma unroll
    for (int mf = 0; mf < 2; ++mf) {
        const int r0m = rb + mf * 16 + g;
        const int r1m = r0m + 8;
#pragma unroll
        for (int ks = 0; ks < 4; ++ks) {
            const int c = ks * 16 + 2 * tg;
            packpair_bf16(Qs[r0m * FSTR + c],     Qs[r0m * FSTR + c + 1],
                          qh[mf][ks][0], ql[mf][ks][0]);
            packpair_bf16(Qs[r1m * FSTR + c],     Qs[r1m * FSTR + c + 1],
                          qh[mf][ks][1], ql[mf][ks][1]);
            packpair_bf16(Qs[r0m * FSTR + c + 8], Qs[r0m * FSTR + c + 9],
                          qh[mf][ks][2], ql[mf][ks][2]);
            packpair_bf16(Qs[r1m * FSTR + c + 8], Qs[r1m * FSTR + c + 9],
                          qh[mf][ks][3], ql[mf][ks][3]);
        }
    }
    __syncthreads();   // frags extracted before stage-1 gets overwritten

    float o[2][8][4];
#pragma unroll
    for (int mf = 0; mf < 2; ++mf)
#pragma unroll
        for (int nf = 0; nf < 8; ++nf)
#pragma unroll
            for (int r = 0; r < 4; ++r) o[mf][nf][r] = 0.f;
    float mM[2][2] = {{-1e30f, -1e30f}, {-1e30f, -1e30f}};
    float lL[2][2] = {{0.f, 0.f}, {0.f, 0.f}};

    for (int kt = 0; kt < ntiles; ++kt) {
        if (kt + 1 < ntiles) {
            issue(kt + 1, (kt + 1) & 1);
            CP_COMMIT();
            CP_WAIT1();
        } else {
            CP_WAIT0();
        }
        __syncthreads();

        const float*    stf = sm + (kt & 1) * ST_WORDS;
        const uint32_t* Kh  = reinterpret_cast<const uint32_t*>(stf);
        const uint32_t* Kl  = Kh + OFF_KL2;
        const float*    Vt  = stf + OFF_VT2;

        // S = Q K^T (3xBF16); each K frag feeds both m-frags
        float s[2][8][4];
#pragma unroll
        for (int mf = 0; mf < 2; ++mf)
#pragma unroll
            for (int nf = 0; nf < 8; ++nf)
#pragma unroll
                for (int r = 0; r < 4; ++r) s[mf][nf][r] = 0.f;

#pragma unroll
        for (int ks = 0; ks < 4; ++ks) {
#pragma unroll
            for (int nf = 0; nf < 8; ++nf) {
                const int cc = nf * 8 + g;
                uint32_t bh[2], bl[2];
                bh[0] = Kh[(ks * 8 + tg) * KSTR + cc];
                bh[1] = Kh[(ks * 8 + tg + 4) * KSTR + cc];
                bl[0] = Kl[(ks * 8 + tg) * KSTR + cc];
                bl[1] = Kl[(ks * 8 + tg + 4) * KSTR + cc];
#pragma unroll
                for (int mf = 0; mf < 2; ++mf) {
                    MMA_BF16(s[mf][nf], ql[mf][ks], bh);
                    MMA_BF16(s[mf][nf], qh[mf][ks], bl);
                    MMA_BF16(s[mf][nf], qh[mf][ks], bh);
                }
            }
        }

        // Causal mask (only the last two tiles of each block have off >= 0)
        const int off = kt * 64 - q0;
        if (off >= 0) {
#pragma unroll
            for (int mf = 0; mf < 2; ++mf) {
                const int r0m = rb + mf * 16 + g;
                const int r1m = r0m + 8;
#pragma unroll
                for (int nf = 0; nf < 8; ++nf) {
                    const int c = nf * 8 + 2 * tg + off;
                    if (c     > r0m) s[mf][nf][0] = -1e30f;
                    if (c + 1 > r0m) s[mf][nf][1] = -1e30f;
                    if (c     > r1m) s[mf][nf][2] = -1e30f;
                    if (c + 1 > r1m) s[mf][nf][3] = -1e30f;
                }
            }
        }

        // Online softmax (base-2), per m-frag
#pragma unroll
        for (int mf = 0; mf < 2; ++mf) {
            float mx0 = -1e30f, mx1 = -1e30f;
#pragma unroll
            for (int nf = 0; nf < 8; ++nf) {
                mx0 = fmaxf(mx0, fmaxf(s[mf][nf][0], s[mf][nf][1]));
                mx1 = fmaxf(mx1, fmaxf(s[mf][nf][2], s[mf][nf][3]));
            }
            mx0 = fmaxf(mx0, __shfl_xor_sync(0xffffffffu, mx0, 1));
            mx0 = fmaxf(mx0, __shfl_xor_sync(0xffffffffu, mx0, 2));
            mx1 = fmaxf(mx1, __shfl_xor_sync(0xffffffffu, mx1, 1));
            mx1 = fmaxf(mx1, __shfl_xor_sync(0xffffffffu, mx1, 2));
            const float mn0 = fmaxf(mM[mf][0], mx0);
            const float mn1 = fmaxf(mM[mf][1], mx1);
            const float a0 = ex2f(mM[mf][0] - mn0);
            const float a1 = ex2f(mM[mf][1] - mn1);

            float rs0 = 0.f, rs1 = 0.f;
#pragma unroll
            for (int nf = 0; nf < 8; ++nf) {
                s[mf][nf][0] = ex2f(s[mf][nf][0] - mn0); rs0 += s[mf][nf][0];
                s[mf][nf][1] = ex2f(s[mf][nf][1] - mn0); rs0 += s[mf][nf][1];
                s[mf][nf][2] = ex2f(s[mf][nf][2] - mn1); rs1 += s[mf][nf][2];
                s[mf][nf][3] = ex2f(s[mf][nf][3] - mn1); rs1 += s[mf][nf][3];
                o[mf][nf][0] *= a0; o[mf][nf][1] *= a0;
                o[mf][nf][2] *= a1; o[mf][nf][3] *= a1;
            }
            rs0 += __shfl_xor_sync(0xffffffffu, rs0, 1);
            rs0 += __shfl_xor_sync(0xffffffffu, rs0, 2);
            rs1 += __shfl_xor_sync(0xffffffffu, rs1, 1);
            rs1 += __shfl_xor_sync(0xffffffffu, rs1, 2);
            lL[mf][0] = lL[mf][0] * a0 + rs0;
            lL[mf][1] = lL[mf][1] * a1 + rs1;
            mM[mf][0] = mn0; mM[mf][1] = mn1;
        }

        // O += P V: shuffle-transpose P per m-frag; each V frag feeds both
        const int src0 = (lane & ~3) | (tg >> 1);
        const int src1 = src0 + 2;
        const bool odd = (tg & 1);
#pragma unroll
        for (int k = 0; k < 8; ++k) {
            uint32_t pa[2][4];
#pragma unroll
            for (int mf = 0; mf < 2; ++mf) {
                float e, d;
                e = __shfl_sync(0xffffffffu, s[mf][k][0], src0);
                d = __shfl_sync(0xffffffffu, s[mf][k][1], src0);
                pa[mf][0] = __float_as_uint(rna_tf32(odd ? d : e));
                e = __shfl_sync(0xffffffffu, s[mf][k][2], src0);
                d = __shfl_sync(0xffffffffu, s[mf][k][3], src0);
                pa[mf][1] = __float_as_uint(rna_tf32(odd ? d : e));
                e = __shfl_sync(0xffffffffu, s[mf][k][0], src1);
                d = __shfl_sync(0xffffffffu, s[mf][k][1], src1);
                pa[mf][2] = __float_as_uint(rna_tf32(odd ? d : e));
                e = __shfl_sync(0xffffffffu, s[mf][k][2], src1);
                d = __shfl_sync(0xffffffffu, s[mf][k][3], src1);
                pa[mf][3] = __float_as_uint(rna_tf32(odd ? d : e));
            }
#pragma unroll
            for (int nf = 0; nf < 8; ++nf) {
                uint32_t vb[2];
                vb[0] = __float_as_uint(Vt[(nf * 8 + g) * FSTR + k * 8 + tg]);
                vb[1] = __float_as_uint(Vt[(nf * 8 + g) * FSTR + k * 8 + tg + 4]);
                MMA_TF32(o[0][nf], pa[0], vb);
                MMA_TF32(o[1][nf], pa[1], vb);
            }
        }
        __syncthreads();   // readers done before next issue reuses buffer
    }

    // Normalize + write ctx packed [D/2][M]
    const int mg = b * T_ + q0;
#pragma unroll
    for (int mf = 0; mf < 2; ++mf) {
        const int r0m = rb + mf * 16 + g;
        const int r1m = r0m + 8;
        const float i0 = 1.f / lL[mf][0];
        const float i1 = 1.f / lL[mf][1];
#pragma unroll
        for (int nf = 0; nf < 8; ++nf) {
            const int col = hh * DH_ + nf * 8 + 2 * tg;
            const size_t kp = (size_t)(col >> 1) * M_;
            uint32_t ph, pl;
            packpair_bf16(o[mf][nf][0] * i0, o[mf][nf][1] * i0, ph, pl);
            g_ch[kp + mg + r0m] = ph;
            g_cl[kp + mg + r0m] = pl;
            packpair_bf16(o[mf][nf][2] * i1, o[mf][nf][3] * i1, ph, pl);
            g_ch[kp + mg + r1m] = ph;
            g_cl[kp + mg + r1m] = pl;
        }
    }
}

// ---------------------------------------------------------------------------
extern "C" void kernel_launch(void* const* d_in, const int* in_sizes, int n_in,
                              void* d_out, int out_size) {
    const float* x  = (const float*)d_in[0];
    const float* Wq = (const float*)d_in[1];
    const float* Wk = (const float*)d_in[2];
    const float* Wv = (const float*)d_in[3];
    const float* Wo = (const float*)d_in[4];
    const float* bo = (const float*)d_in[5];
    float* out = (float*)d_out;

    // 0) Pack x and weights
    pack_x<<<dim3(M_ / 32, KP_ / 32), dim3(32, 8)>>>(x);
    pack_w<<<dim3(N_ / 256, KP_, 4), 256>>>(Wq, Wk, Wv, Wo);

    const int gsmem = STAGES * ST_U32 * 4;
    cudaFuncSetAttribute(tgemm_qkv,
                         cudaFuncAttributeMaxDynamicSharedMemorySize, gsmem);
    cudaFuncSetAttribute(tgemm_out,
                         cudaFuncAttributeMaxDynamicSharedMemorySize, gsmem);

    // 1) QKV projections with fused K-pack / V-transpose epilogues
    tgemm_qkv<<<dim3(N_ / 128, M_ / 128, 3), 256, gsmem>>>();

    // 2) Attention (mf=2, 4 warps; writes packed ctx)
    const int asmem = SM_ATT * sizeof(float);   // 71,680 B
    cudaFuncSetAttribute(flash_attn_tc,
                         cudaFuncAttributeMaxDynamicSharedMemorySize, asmem);
    flash_attn_tc<<<dim3(T_ / 128, H_, B_), 128, asmem>>>();

    // 3) Output projection (+bias)
    tgemm_out<<<dim3(N_ / 128, M_ / 128), 256, gsmem>>>(bo, out);
}